// round 8
// baseline (speedup 1.0000x reference)
#include <cuda_runtime.h>
#include <cuda_bf16.h>
#include <cstdint>

// Problem constants
#define NB    4
#define SEQ   2048
#define DIM   1024
#define HEADS 16
#define HD    64
#define NS    (NB*SEQ)
#define NH    (NB*HEADS)
#define NEGC  1000000000.0f
#define LOG2E 1.4426950408889634f
#define SHIFT2 (8.0f * LOG2E)     // fixed softmax shift in log2 domain

// ---------------------------------------------------------------------------
// Scratch (device globals)
// ---------------------------------------------------------------------------
__device__ __align__(16) float g_vo [(size_t)NS * DIM];
__device__ __align__(16) float g_pvo[(size_t)NS * DIM];
__device__ __align__(16) float g_vsum[NB][8][DIM];
__device__ __align__(16) __nv_bfloat16 g_qb[(size_t)NH * SEQ * HD];
__device__ __align__(16) __nv_bfloat16 g_kb[(size_t)NH * SEQ * HD];
__device__ __align__(16) __nv_bfloat16 g_vb[(size_t)NH * SEQ * HD];
__device__ __align__(16) __nv_bfloat16 g_xh[(size_t)NS * DIM];
__device__ __align__(16) __nv_bfloat16 g_xl[(size_t)NS * DIM];
__device__ __align__(16) __nv_bfloat16 g_ab[(size_t)NS * DIM];
__device__ __align__(16) __nv_bfloat16 g_wh[(size_t)4 * DIM * DIM];
__device__ __align__(16) __nv_bfloat16 g_wl[(size_t)4 * DIM * DIM];
__device__ __align__(16) __nv_bfloat16 g_wvt_h[(size_t)DIM * DIM];
__device__ __align__(16) __nv_bfloat16 g_wvt_l[(size_t)DIM * DIM];
__device__ __align__(16) __nv_bfloat16 g_wvoh[(size_t)DIM * DIM];
__device__ __align__(16) __nv_bfloat16 g_wvol[(size_t)DIM * DIM];

// ---------------------------------------------------------------------------
// PTX helpers
// ---------------------------------------------------------------------------
__device__ __forceinline__ uint32_t smem_to_u32(const void* p) {
    uint32_t a;
    asm("{ .reg .u64 t; cvta.to.shared.u64 t, %1; cvt.u32.u64 %0, t; }"
        : "=r"(a) : "l"(p));
    return a;
}

#define CP16(dst, src) \
    asm volatile("cp.async.cg.shared.global [%0], [%1], 16;" \
                 :: "r"((uint32_t)(dst)), "l"(src))
#define CP_COMMIT() asm volatile("cp.async.commit_group;" ::: "memory")
#define CP_WAIT0()  asm volatile("cp.async.wait_group 0;" ::: "memory")
#define CP_WAIT1()  asm volatile("cp.async.wait_group 1;" ::: "memory")

#define LDSM_X4(r, addr) \
    asm volatile("ldmatrix.sync.aligned.m8n8.x4.shared.b16 {%0,%1,%2,%3}, [%4];" \
        : "=r"((r)[0]), "=r"((r)[1]), "=r"((r)[2]), "=r"((r)[3]) : "r"(addr))

#define LDSM_X4_T(r, addr) \
    asm volatile("ldmatrix.sync.aligned.m8n8.x4.trans.shared.b16 {%0,%1,%2,%3}, [%4];" \
        : "=r"((r)[0]), "=r"((r)[1]), "=r"((r)[2]), "=r"((r)[3]) : "r"(addr))

#define MMA_BF16(c, a, b0, b1) \
    asm volatile("mma.sync.aligned.m16n8k16.row.col.f32.bf16.bf16.f32 " \
        "{%0,%1,%2,%3}, {%4,%5,%6,%7}, {%8,%9}, {%0,%1,%2,%3};" \
        : "+f"((c)[0]), "+f"((c)[1]), "+f"((c)[2]), "+f"((c)[3]) \
        : "r"((a)[0]), "r"((a)[1]), "r"((a)[2]), "r"((a)[3]), "r"(b0), "r"(b1))

__device__ __forceinline__ uint32_t packbf2(float lo, float hi) {
    __nv_bfloat162 t = __floats2bfloat162_rn(lo, hi);
    return *reinterpret_cast<uint32_t*>(&t);
}

// ---------------------------------------------------------------------------
// bf16 split helpers / kernels
// ---------------------------------------------------------------------------
__device__ __forceinline__ void split4(float4 v, __nv_bfloat16* h, __nv_bfloat16* l)
{
    h[0] = __float2bfloat16(v.x); l[0] = __float2bfloat16(v.x - __bfloat162float(h[0]));
    h[1] = __float2bfloat16(v.y); l[1] = __float2bfloat16(v.y - __bfloat162float(h[1]));
    h[2] = __float2bfloat16(v.z); l[2] = __float2bfloat16(v.z - __bfloat162float(h[2]));
    h[3] = __float2bfloat16(v.w); l[3] = __float2bfloat16(v.w - __bfloat162float(h[3]));
}

__global__ void __launch_bounds__(256) split_x_kernel(const float* __restrict__ x)
{
    size_t i = ((size_t)blockIdx.x * 256 + threadIdx.x) * 4;
    float4 v = *(const float4*)(x + i);
    __nv_bfloat16 h[4], l[4];
    split4(v, h, l);
    *(uint2*)(g_xh + i) = *(uint2*)h;
    *(uint2*)(g_xl + i) = *(uint2*)l;
}

__global__ void __launch_bounds__(256) split_w_kernel(
    const float* __restrict__ wq, const float* __restrict__ wk,
    const float* __restrict__ wv, const float* __restrict__ wo)
{
    const float* w = (blockIdx.y == 0) ? wq : (blockIdx.y == 1) ? wk
                   : (blockIdx.y == 2) ? wv : wo;
    size_t base = (size_t)blockIdx.y * DIM * DIM;
    size_t i = ((size_t)blockIdx.x * 256 + threadIdx.x) * 4;
    float4 v = *(const float4*)(w + i);
    __nv_bfloat16 h[4], l[4];
    split4(v, h, l);
    *(uint2*)(g_wh + base + i) = *(uint2*)h;
    *(uint2*)(g_wl + base + i) = *(uint2*)l;
}

__global__ void __launch_bounds__(256) transpose_wv_kernel(const float* __restrict__ wv)
{
    __shared__ float tile[32][33];
    const int bx = blockIdx.x * 32;
    const int by = blockIdx.y * 32;
    const int tx = threadIdx.x & 31, ty = threadIdx.x >> 5;
    #pragma unroll
    for (int i = 0; i < 4; i++)
        tile[ty + 8*i][tx] = wv[(size_t)(by + ty + 8*i) * DIM + bx + tx];
    __syncthreads();
    #pragma unroll
    for (int i = 0; i < 4; i++) {
        float v = tile[tx][ty + 8*i];
        __nv_bfloat16 h = __float2bfloat16(v);
        __nv_bfloat16 l = __float2bfloat16(v - __bfloat162float(h));
        size_t o = (size_t)(bx + ty + 8*i) * DIM + by + tx;
        g_wvt_h[o] = h;
        g_wvt_l[o] = l;
    }
}

// ---------------------------------------------------------------------------
// 3-stage cp.async mma.sync GEMM: C(128x128)=A@B^T, 8 warps (2m x 4n),
// warp tile 64x32, BK=32. X3: AhBh + AlBh + AhBl.
// ---------------------------------------------------------------------------
#define PGP   40
#define TILEB (128*PGP*2)

template<bool X3>
__device__ __forceinline__ void gemm128_pipe(
    const __nv_bfloat16* __restrict__ Agh, const __nv_bfloat16* __restrict__ Agl,
    const __nv_bfloat16* __restrict__ Bgh, const __nv_bfloat16* __restrict__ Bgl,
    int row0, int col0, int kdim, uint32_t sm, float acc[4][4][4])
{
    const int tid = threadIdx.x, lane = tid & 31, wid = tid >> 5;
    const int warp_m = (wid >> 2) * 64, warp_n = (wid & 3) * 32;
    const int STAGE = (X3 ? 4 : 2) * TILEB;
    const int lr = tid >> 2;
    const int lc = (tid & 3) * 8;
    const uint32_t so1 = (uint32_t)((lr * PGP + lc) * 2);
    const uint32_t so2 = (uint32_t)(((lr + 64) * PGP + lc) * 2);

    auto issue = [&](int kt, int buf) {
        uint32_t base = sm + buf * STAGE;
        const __nv_bfloat16* agh = Agh + (size_t)(row0 + lr) * kdim + kt * 32 + lc;
        const __nv_bfloat16* bgh = Bgh + (size_t)(col0 + lr) * kdim + kt * 32 + lc;
        CP16(base + so1, agh);
        CP16(base + so2, agh + 64 * kdim);
        uint32_t bb = base + (X3 ? 2 : 1) * TILEB;
        CP16(bb + so1, bgh);
        CP16(bb + so2, bgh + 64 * kdim);
        if (X3) {
            const __nv_bfloat16* agl = Agl + (size_t)(row0 + lr) * kdim + kt * 32 + lc;
            const __nv_bfloat16* bgl = Bgl + (size_t)(col0 + lr) * kdim + kt * 32 + lc;
            CP16(base + TILEB + so1, agl);
            CP16(base + TILEB + so2, agl + 64 * kdim);
            CP16(base + 3 * TILEB + so1, bgl);
            CP16(base + 3 * TILEB + so2, bgl + 64 * kdim);
        }
        CP_COMMIT();
    };

    const int nkt = kdim / 32;
    issue(0, 0);
    if (nkt > 1) issue(1, 1);

    for (int kt = 0; kt < nkt; kt++) {
        if (kt == nkt - 1) { CP_WAIT0(); } else { CP_WAIT1(); }
        __syncthreads();
        if (kt + 2 < nkt) issue(kt + 2, (kt + 2) % 3);

        const uint32_t ah_b = sm + (kt % 3) * STAGE;
        const uint32_t al_b = ah_b + TILEB;
        const uint32_t bh_b = ah_b + (X3 ? 2 : 1) * TILEB;
        const uint32_t bl_b = ah_b + 3 * TILEB;

        #pragma unroll
        for (int ks = 0; ks < 2; ks++) {
            uint32_t af[4][4], bfh[2][4];
            #pragma unroll
            for (int mt = 0; mt < 4; mt++) {
                uint32_t ad = ah_b + (uint32_t)(((warp_m + mt*16 + (lane&15))*PGP + ks*16)*2 + (lane&16));
                LDSM_X4(af[mt], ad);
            }
            #pragma unroll
            for (int p = 0; p < 2; p++) {
                uint32_t bd = bh_b + (uint32_t)(((warp_n + p*16 + (lane&7) + ((lane&16)>>1))*PGP + ks*16)*2 + ((lane&8)<<1));
                LDSM_X4(bfh[p], bd);
            }
            #pragma unroll
            for (int mt = 0; mt < 4; mt++)
                #pragma unroll
                for (int p = 0; p < 2; p++) {
                    MMA_BF16(acc[mt][2*p],   af[mt], bfh[p][0], bfh[p][1]);
                    MMA_BF16(acc[mt][2*p+1], af[mt], bfh[p][2], bfh[p][3]);
                }
            if (X3) {
                {
                    uint32_t alf[4][4];
                    #pragma unroll
                    for (int mt = 0; mt < 4; mt++) {
                        uint32_t ad = al_b + (uint32_t)(((warp_m + mt*16 + (lane&15))*PGP + ks*16)*2 + (lane&16));
                        LDSM_X4(alf[mt], ad);
                    }
                    #pragma unroll
                    for (int mt = 0; mt < 4; mt++)
                        #pragma unroll
                        for (int p = 0; p < 2; p++) {
                            MMA_BF16(acc[mt][2*p],   alf[mt], bfh[p][0], bfh[p][1]);
                            MMA_BF16(acc[mt][2*p+1], alf[mt], bfh[p][2], bfh[p][3]);
                        }
                }
                {
                    uint32_t blf[2][4];
                    #pragma unroll
                    for (int p = 0; p < 2; p++) {
                        uint32_t bd = bl_b + (uint32_t)(((warp_n + p*16 + (lane&7) + ((lane&16)>>1))*PGP + ks*16)*2 + ((lane&8)<<1));
                        LDSM_X4(blf[p], bd);
                    }
                    #pragma unroll
                    for (int mt = 0; mt < 4; mt++)
                        #pragma unroll
                        for (int p = 0; p < 2; p++) {
                            MMA_BF16(acc[mt][2*p],   af[mt], blf[p][0], blf[p][1]);
                            MMA_BF16(acc[mt][2*p+1], af[mt], blf[p][2], blf[p][3]);
                        }
                }
            }
        }
    }
}

// ---------------------------------------------------------------------------
// QKV projection (x1). grid (8, 64, 3). Q folds 0.125*log2e.
// ---------------------------------------------------------------------------
__global__ void __launch_bounds__(256, 2) proj_qkv_kernel()
{
    extern __shared__ char smraw[];
    uint32_t sm = smem_to_u32(smraw);
    const int z = blockIdx.z;
    const __nv_bfloat16* Bh = g_wh + (size_t)z * DIM * DIM;
    __nv_bfloat16* dst = (z == 0) ? g_qb : (z == 1) ? g_kb : g_vb;
    const float scale = (z == 0) ? 0.125f * LOG2E : 1.0f;
    const int row0 = blockIdx.y * 128, col0 = blockIdx.x * 128;

    float acc[4][4][4] = {};
    gemm128_pipe<false>(g_xh, nullptr, Bh, nullptr, row0, col0, DIM, sm, acc);

    const int lane = threadIdx.x & 31, wid = threadIdx.x >> 5;
    const int warp_m = (wid >> 2) * 64, warp_n = (wid & 3) * 32;
    #pragma unroll
    for (int mt = 0; mt < 4; mt++) {
        int r0 = row0 + warp_m + mt*16 + (lane >> 2);
        #pragma unroll
        for (int nt = 0; nt < 4; nt++) {
            int col = col0 + warp_n + nt*8 + (lane & 3) * 2;
            int h = col >> 6, dd = col & 63;
            #pragma unroll
            for (int half = 0; half < 2; half++) {
                int r = r0 + half*8;
                int n = r >> 11, s = r & (SEQ - 1);
                __nv_bfloat162 hv = __floats2bfloat162_rn(acc[mt][nt][2*half]*scale,
                                                          acc[mt][nt][2*half+1]*scale);
                *(__nv_bfloat162*)(dst + (((size_t)(n*HEADS + h)*SEQ + s))*HD + dd) = hv;
            }
        }
    }
}

// ---------------------------------------------------------------------------
// Wvo = Wo @ Wv (x3). grid (8, 8). Emits hi/lo split.
// ---------------------------------------------------------------------------
__global__ void __launch_bounds__(256) wvo_kernel()
{
    extern __shared__ char smraw[];
    uint32_t sm = smem_to_u32(smraw);
    const __nv_bfloat16* Ah = g_wh + (size_t)3 * DIM * DIM;
    const __nv_bfloat16* Al = g_wl + (size_t)3 * DIM * DIM;
    const int row0 = blockIdx.y * 128, col0 = blockIdx.x * 128;

    float acc[4][4][4] = {};
    gemm128_pipe<true>(Ah, Al, g_wvt_h, g_wvt_l, row0, col0, DIM, sm, acc);

    const int lane = threadIdx.x & 31, wid = threadIdx.x >> 5;
    const int warp_m = (wid >> 2) * 64, warp_n = (wid & 3) * 32;
    #pragma unroll
    for (int mt = 0; mt < 4; mt++) {
        int r0 = row0 + warp_m + mt*16 + (lane >> 2);
        #pragma unroll
        for (int nt = 0; nt < 4; nt++) {
            int col = col0 + warp_n + nt*8 + (lane & 3) * 2;
            #pragma unroll
            for (int half = 0; half < 2; half++) {
                int r = r0 + half*8;
                float vx = acc[mt][nt][2*half], vy = acc[mt][nt][2*half+1];
                __nv_bfloat16 hx = __float2bfloat16(vx);
                __nv_bfloat16 hy = __float2bfloat16(vy);
                __nv_bfloat16 lx = __float2bfloat16(vx - __bfloat162float(hx));
                __nv_bfloat16 ly = __float2bfloat16(vy - __bfloat162float(hy));
                size_t o = (size_t)r * DIM + col;
                __nv_bfloat162 hv; hv.x = hx; hv.y = hy;
                __nv_bfloat162 lv; lv.x = lx; lv.y = ly;
                *(__nv_bfloat162*)(g_wvoh + o) = hv;
                *(__nv_bfloat162*)(g_wvol + o) = lv;
            }
        }
    }
}

// ---------------------------------------------------------------------------
// vo = X @ Wvo^T (x3). grid (8, 64). fp32 out.
// ---------------------------------------------------------------------------
__global__ void __launch_bounds__(256) vo_kernel()
{
    extern __shared__ char smraw[];
    uint32_t sm = smem_to_u32(smraw);
    const int row0 = blockIdx.y * 128, col0 = blockIdx.x * 128;

    float acc[4][4][4] = {};
    gemm128_pipe<true>(g_xh, g_xl, g_wvoh, g_wvol, row0, col0, DIM, sm, acc);

    const int lane = threadIdx.x & 31, wid = threadIdx.x >> 5;
    const int warp_m = (wid >> 2) * 64, warp_n = (wid & 3) * 32;
    #pragma unroll
    for (int mt = 0; mt < 4; mt++) {
        int r0 = row0 + warp_m + mt*16 + (lane >> 2);
        #pragma unroll
        for (int nt = 0; nt < 4; nt++) {
            int col = col0 + warp_n + nt*8 + (lane & 3) * 2;
            #pragma unroll
            for (int half = 0; half < 2; half++) {
                int r = r0 + half*8;
                float2 f2 = {acc[mt][nt][2*half], acc[mt][nt][2*half+1]};
                *(float2*)(g_vo + (size_t)r * DIM + col) = f2;
            }
        }
    }
}

// ---------------------------------------------------------------------------
// Output projection (x1) + bias + correction.
// ---------------------------------------------------------------------------
__global__ void __launch_bounds__(256, 2) proj_out_kernel(
    const float* __restrict__ bo, float* __restrict__ out)
{
    extern __shared__ char smraw[];
    uint32_t sm = smem_to_u32(smraw);
    const __nv_bfloat16* Bh = g_wh + (size_t)3 * DIM * DIM;
    const int row0 = blockIdx.y * 128, col0 = blockIdx.x * 128;

    float acc[4][4][4] = {};
    gemm128_pipe<false>(g_ab, nullptr, Bh, nullptr, row0, col0, DIM, sm, acc);

    const int lane = threadIdx.x & 31, wid = threadIdx.x >> 5;
    const int warp_m = (wid >> 2) * 64, warp_n = (wid & 3) * 32;
    #pragma unroll
    for (int mt = 0; mt < 4; mt++) {
        int r0 = row0 + warp_m + mt*16 + (lane >> 2);
        #pragma unroll
        for (int nt = 0; nt < 4; nt++) {
            int col = col0 + warp_n + nt*8 + (lane & 3) * 2;
            float2 bb = *(const float2*)(bo + col);
            #pragma unroll
            for (int half = 0; half < 2; half++) {
                int r = r0 + half*8;
                float2 pv = *(const float2*)(g_pvo + (size_t)r * DIM + col);
                float2 f2 = {acc[mt][nt][2*half]   + bb.x + pv.x,
                             acc[mt][nt][2*half+1] + bb.y + pv.y};
                *(float2*)(out + (size_t)r * DIM + col) = f2;
            }
        }
    }
}

// ---------------------------------------------------------------------------
// Exclusive prefix of vo (two-pass), scaled by -1e9.
// ---------------------------------------------------------------------------
__global__ void __launch_bounds__(256) prefix_a_kernel()
{
    const int n = blockIdx.x, ch = blockIdx.y;
    const int d = blockIdx.z * 256 + threadIdx.x;
    const float* p = g_vo + ((size_t)(n * SEQ) + ch * 256) * DIM + d;
    float s = 0.0f;
    for (int t = 0; t < 256; t++) s += p[(size_t)t * DIM];
    g_vsum[n][ch][d] = s;
}
__global__ void __launch_bounds__(256) prefix_b_kernel()
{
    const int n = blockIdx.x, ch = blockIdx.y;
    const int d = blockIdx.z * 256 + threadIdx.x;
    float run = 0.0f;
    for (int c = 0; c < ch; c++) run += g_vsum[n][c][d];
    const float* p = g_vo  + ((size_t)(n * SEQ) + ch * 256) * DIM + d;
    float*       q = g_pvo + ((size_t)(n * SEQ) + ch * 256) * DIM + d;
    for (int t = 0; t < 256; t++) {
        q[(size_t)t * DIM] = -NEGC * run;
        run += p[(size_t)t * DIM];
    }
}

// ---------------------------------------------------------------------------
// Flash attention, 3-stage KV pipeline, fixed-shift exp2 softmax.
// grid (16, 64), 256 threads. smem = 73728 B.
// ---------------------------------------------------------------------------
#define AP 72
#define AQ_BYTES (128*AP*2)
#define AKV_BYTES (64*AP*2)
#define AKV_STAGE (2*AKV_BYTES)
#define ATTN_SMEM (AQ_BYTES + 3*AKV_STAGE)

__global__ void __launch_bounds__(256, 2) attn_kernel()
{
    extern __shared__ char smraw[];
    const uint32_t sm = smem_to_u32(smraw);
    const uint32_t qs_b = sm;
    const int tid = threadIdx.x, lane = tid & 31, wid = tid >> 5;
    const int nh = blockIdx.y, q0 = blockIdx.x * 128;
    const __nv_bfloat16* qg = g_qb + (size_t)nh * SEQ * HD;
    const __nv_bfloat16* kg = g_kb + (size_t)nh * SEQ * HD;
    const __nv_bfloat16* vg = g_vb + (size_t)nh * SEQ * HD;

    const int lr = tid >> 3;
    const int lc = (tid & 7) * 8;
    const uint32_t kvo1 = (uint32_t)((lr * AP + lc) * 2);
    const uint32_t kvo2 = (uint32_t)(((lr + 32) * AP + lc) * 2);

    auto issue_kv = [&](int kt, int buf) {
        uint32_t base = sm + AQ_BYTES + buf * AKV_STAGE;
        const __nv_bfloat16* kp = kg + (size_t)(kt*64 + lr) * HD + lc;
        const __nv_bfloat16* vp = vg + (size_t)(kt*64 + lr) * HD + lc;
        CP16(base + kvo1, kp);
        CP16(base + kvo2, kp + 32 * HD);
        CP16(base + AKV_BYTES + kvo1, vp);
        CP16(base + AKV_BYTES + kvo2, vp + 32 * HD);
        CP_COMMIT();
    };

    {
        const int qr = tid >> 3, qc = (tid & 7) * 8;
        #pragma unroll
        for (int i = 0; i < 4; i++) {
            int r = qr + i * 32;
            CP16(qs_b + (uint32_t)((r * AP + qc) * 2), qg + (size_t)(q0 + r) * HD + qc);
        }
    }
    issue_kv(0, 0);
    issue_kv(1, 1);

    uint32_t qf[4][4];
    const int m0 = wid * 16;
    float o[8][4] = {};
    float lr0 = 0.0f, lr1 = 0.0f;
    const int NKT = SEQ / 64;

    for (int kt = 0; kt < NKT; kt++) {
        if (kt == NKT - 1) { CP_WAIT0(); } else { CP_WAIT1(); }
        __syncthreads();
        if (kt + 2 < NKT) issue_kv(kt + 2, (kt + 2) % 3);

        if (kt == 0) {
            #pragma unroll
            for (int ks = 0; ks < 4; ks++) {
                uint32_t ad = qs_b + (uint32_t)(((m0 + (lane&15))*AP + ks*16)*2 + (lane&16));
                LDSM_X4(qf[ks], ad);
            }
        }

        const uint32_t ks_b = sm + AQ_BYTES + (kt % 3) * AKV_STAGE;
        const uint32_t vs_b = ks_b + AKV_BYTES;

        // S = Q K^T (log2-domain logits: Q pre-scaled by 0.125*log2e)
        float sf[8][4] = {};
        #pragma unroll
        for (int ks = 0; ks < 4; ks++) {
            uint32_t bfr[4][4];
            #pragma unroll
            for (int p = 0; p < 4; p++) {
                uint32_t bd = ks_b + (uint32_t)(((p*16 + (lane&7) + ((lane&16)>>1))*AP + ks*16)*2 + ((lane&8)<<1));
                LDSM_X4(bfr[p], bd);
            }
            #pragma unroll
            for (int p = 0; p < 4; p++) {
                MMA_BF16(sf[2*p],   qf[ks], bfr[p][0], bfr[p][1]);
                MMA_BF16(sf[2*p+1], qf[ks], bfr[p][2], bfr[p][3]);
            }
        }

        // p = exp2(s' - SHIFT2) == exp(s - 8); no max, no rescale
        uint32_t pf[4][4];
        #pragma unroll
        for (int g = 0; g < 4; g++) {
            float e00 = exp2f(sf[2*g][0]   - SHIFT2), e01 = exp2f(sf[2*g][1]   - SHIFT2);
            float e02 = exp2f(sf[2*g][2]   - SHIFT2), e03 = exp2f(sf[2*g][3]   - SHIFT2);
            float e10 = exp2f(sf[2*g+1][0] - SHIFT2), e11 = exp2f(sf[2*g+1][1] - SHIFT2);
            float e12 = exp2f(sf[2*g+1][2] - SHIFT2), e13 = exp2f(sf[2*g+1][3] - SHIFT2);
            lr0 += (e00 + e01) + (e10 + e11);
            lr1 += (e02 + e03) + (e12 + e13);
            pf[g][0] = packbf2(e00, e01);
            pf[g][1] = packbf2(e02, e03);
            pf[g][2] = packbf2(e10, e11);
            pf[g][3] = packbf2(e12, e13);
        }

        // O += P @ V
        #pragma unroll
        for (int g = 0; g < 4; g++) {
            uint32_t vf[4][4];
            #pragma unroll
            for (int p = 0; p < 4; p++) {
                uint32_t vd = vs_b + (uint32_t)(((g*16 + (lane&7) + (lane&8))*AP + p*16)*2 + (lane&16));
                LDSM_X4_T(vf[p], vd);
            }
            #pragma unroll
            for (int p = 0; p < 4; p++) {
                MMA_BF16(o[2*p],   pf[g], vf[p][0], vf[p][1]);
                MMA_BF16(o[2*p+1], pf[g], vf[p][2], vf[p][3]);
            }
        }
    }

    lr0 += __shfl_xor_sync(0xffffffffu, lr0, 1);
    lr0 += __shfl_xor_sync(0xffffffffu, lr0, 2);
    lr1 += __shfl_xor_sync(0xffffffffu, lr1, 1);
    lr1 += __shfl_xor_sync(0xffffffffu, lr1, 2);
    const float i0 = 1.0f / lr0, i1 = 1.0f / lr1;

    const int n = nh >> 4, hh = nh & 15;
    const int srow0 = q0 + m0 + (lane >> 2);
    #pragma unroll
    for (int nt = 0; nt < 8; nt++) {
        int dd = nt*8 + (lane & 3) * 2;
        #pragma unroll
        for (int half = 0; half < 2; half++) {
            int s = srow0 + half*8;
            float inv = half ? i1 : i0;
            __nv_bfloat162 hv = __floats2bfloat162_rn(o[nt][2*half] * inv,
                                                      o[nt][2*half+1] * inv);
            *(__nv_bfloat162*)(g_ab + ((size_t)(n * SEQ + s)) * DIM + hh * HD + dd) = hv;
        }
    }
}

// ---------------------------------------------------------------------------
extern "C" void kernel_launch(void* const* d_in, const int* in_sizes, int n_in,
                              void* d_out, int out_size)
{
    const float* x  = (const float*)d_in[0];
    const float* wq = (const float*)d_in[1];
    const float* wk = (const float*)d_in[2];
    const float* wv = (const float*)d_in[3];
    const float* wo = (const float*)d_in[4];
    const float* bo = (const float*)d_in[5];
    float* out = (float*)d_out;

    const int SM_X1 = 3 * 2 * TILEB;          // 61440
    const int SM_X3 = 3 * 4 * TILEB;          // 122880

    cudaFuncSetAttribute(proj_qkv_kernel,
                         cudaFuncAttributeMaxDynamicSharedMemorySize, SM_X1);
    cudaFuncSetAttribute(wvo_kernel,
                         cudaFuncAttributeMaxDynamicSharedMemorySize, SM_X3);
    cudaFuncSetAttribute(vo_kernel,
                         cudaFuncAttributeMaxDynamicSharedMemorySize, SM_X3);
    cudaFuncSetAttribute(proj_out_kernel,
                         cudaFuncAttributeMaxDynamicSharedMemorySize, SM_X1);
    cudaFuncSetAttribute(attn_kernel,
                         cudaFuncAttributeMaxDynamicSharedMemorySize, ATTN_SMEM);

    split_x_kernel<<<NS*DIM/(256*4), 256>>>(x);
    split_w_kernel<<<dim3(DIM*DIM/(256*4), 4), 256>>>(wq, wk, wv, wo);
    transpose_wv_kernel<<<dim3(32, 32), 256>>>(wv);
    wvo_kernel<<<dim3(DIM/128, DIM/128), 256, SM_X3>>>();
    proj_qkv_kernel<<<dim3(DIM/128, NS/128, 3), 256, SM_X1>>>();
    vo_kernel<<<dim3(DIM/128, NS/128), 256, SM_X3>>>();
    prefix_a_kernel<<<dim3(NB, 8, 4), 256>>>();
    prefix_b_kernel<<<dim3(NB, 8, 4), 256>>>();
    attn_kernel<<<dim3(SEQ/128, NH), 256, ATTN_SMEM>>>();
    proj_out_kernel<<<dim3(DIM/128, NS/128), 256, SM_X1>>>(bo, out);
}

// round 9
// speedup vs baseline: 1.0824x; 1.0824x over previous
#include <cuda_runtime.h>
#include <cuda_bf16.h>
#include <cstdint>

// Problem constants
#define NB    4
#define SEQ   2048
#define DIM   1024
#define HEADS 16
#define HD    64
#define NS    (NB*SEQ)
#define NH    (NB*HEADS)
#define NEGC  1000000000.0f
#define LOG2E 1.4426950408889634f
#define SHIFT2 (8.0f * LOG2E)

// ---------------------------------------------------------------------------
// Scratch (device globals)
// ---------------------------------------------------------------------------
#define WVO_SPLIT 8
__device__ __align__(16) float g_vo  [(size_t)NS * DIM];
__device__ __align__(16) float g_pvo [(size_t)NS * DIM];
__device__ __align__(16) float g_vsum[NB][8][DIM];
__device__ __align__(16) float g_wvop[(size_t)WVO_SPLIT * DIM * DIM];  // split-K partials
__device__ __align__(16) __nv_bfloat16 g_qb[(size_t)NH * SEQ * HD];
__device__ __align__(16) __nv_bfloat16 g_kb[(size_t)NH * SEQ * HD];
__device__ __align__(16) __nv_bfloat16 g_vb[(size_t)NH * SEQ * HD];
__device__ __align__(16) __nv_bfloat16 g_xh[(size_t)NS * DIM];
__device__ __align__(16) __nv_bfloat16 g_xl[(size_t)NS * DIM];
__device__ __align__(16) __nv_bfloat16 g_ab[(size_t)NS * DIM];
__device__ __align__(16) __nv_bfloat16 g_wh[(size_t)4 * DIM * DIM];
__device__ __align__(16) __nv_bfloat16 g_wl[(size_t)4 * DIM * DIM];
__device__ __align__(16) __nv_bfloat16 g_wvt_h[(size_t)DIM * DIM];
__device__ __align__(16) __nv_bfloat16 g_wvt_l[(size_t)DIM * DIM];
__device__ __align__(16) __nv_bfloat16 g_wvoh[(size_t)DIM * DIM];
__device__ __align__(16) __nv_bfloat16 g_wvol[(size_t)DIM * DIM];

// ---------------------------------------------------------------------------
// PTX helpers
// ---------------------------------------------------------------------------
__device__ __forceinline__ uint32_t smem_to_u32(const void* p) {
    uint32_t a;
    asm("{ .reg .u64 t; cvta.to.shared.u64 t, %1; cvt.u32.u64 %0, t; }"
        : "=r"(a) : "l"(p));
    return a;
}

#define CP16(dst, src) \
    asm volatile("cp.async.cg.shared.global [%0], [%1], 16;" \
                 :: "r"((uint32_t)(dst)), "l"(src))
#define CP_COMMIT() asm volatile("cp.async.commit_group;" ::: "memory")
#define CP_WAIT0()  asm volatile("cp.async.wait_group 0;" ::: "memory")

#define LDSM_X4(r, addr) \
    asm volatile("ldmatrix.sync.aligned.m8n8.x4.shared.b16 {%0,%1,%2,%3}, [%4];" \
        : "=r"((r)[0]), "=r"((r)[1]), "=r"((r)[2]), "=r"((r)[3]) : "r"(addr))

#define LDSM_X4_T(r, addr) \
    asm volatile("ldmatrix.sync.aligned.m8n8.x4.trans.shared.b16 {%0,%1,%2,%3}, [%4];" \
        : "=r"((r)[0]), "=r"((r)[1]), "=r"((r)[2]), "=r"((r)[3]) : "r"(addr))

#define MMA_BF16(c, a, b0, b1) \
    asm volatile("mma.sync.aligned.m16n8k16.row.col.f32.bf16.bf16.f32 " \
        "{%0,%1,%2,%3}, {%4,%5,%6,%7}, {%8,%9}, {%0,%1,%2,%3};" \
        : "+f"((c)[0]), "+f"((c)[1]), "+f"((c)[2]), "+f"((c)[3]) \
        : "r"((a)[0]), "r"((a)[1]), "r"((a)[2]), "r"((a)[3]), "r"(b0), "r"(b1))

__device__ __forceinline__ uint32_t packbf2(float lo, float hi) {
    __nv_bfloat162 t = __floats2bfloat162_rn(lo, hi);
    return *reinterpret_cast<uint32_t*>(&t);
}

// ---------------------------------------------------------------------------
// bf16 split helpers / kernels
// ---------------------------------------------------------------------------
__device__ __forceinline__ void split4(float4 v, __nv_bfloat16* h, __nv_bfloat16* l)
{
    h[0] = __float2bfloat16(v.x); l[0] = __float2bfloat16(v.x - __bfloat162float(h[0]));
    h[1] = __float2bfloat16(v.y); l[1] = __float2bfloat16(v.y - __bfloat162float(h[1]));
    h[2] = __float2bfloat16(v.z); l[2] = __float2bfloat16(v.z - __bfloat162float(h[2]));
    h[3] = __float2bfloat16(v.w); l[3] = __float2bfloat16(v.w - __bfloat162float(h[3]));
}

__global__ void __launch_bounds__(256) split_x_kernel(const float* __restrict__ x)
{
    size_t i = ((size_t)blockIdx.x * 256 + threadIdx.x) * 4;
    float4 v = *(const float4*)(x + i);
    __nv_bfloat16 h[4], l[4];
    split4(v, h, l);
    *(uint2*)(g_xh + i) = *(uint2*)h;
    *(uint2*)(g_xl + i) = *(uint2*)l;
}

__global__ void __launch_bounds__(256) split_w_kernel(
    const float* __restrict__ wq, const float* __restrict__ wk,
    const float* __restrict__ wv, const float* __restrict__ wo)
{
    const float* w = (blockIdx.y == 0) ? wq : (blockIdx.y == 1) ? wk
                   : (blockIdx.y == 2) ? wv : wo;
    size_t base = (size_t)blockIdx.y * DIM * DIM;
    size_t i = ((size_t)blockIdx.x * 256 + threadIdx.x) * 4;
    float4 v = *(const float4*)(w + i);
    __nv_bfloat16 h[4], l[4];
    split4(v, h, l);
    *(uint2*)(g_wh + base + i) = *(uint2*)h;
    *(uint2*)(g_wl + base + i) = *(uint2*)l;
}

__global__ void __launch_bounds__(256) transpose_wv_kernel(const float* __restrict__ wv)
{
    __shared__ float tile[32][33];
    const int bx = blockIdx.x * 32;
    const int by = blockIdx.y * 32;
    const int tx = threadIdx.x & 31, ty = threadIdx.x >> 5;
    #pragma unroll
    for (int i = 0; i < 4; i++)
        tile[ty + 8*i][tx] = wv[(size_t)(by + ty + 8*i) * DIM + bx + tx];
    __syncthreads();
    #pragma unroll
    for (int i = 0; i < 4; i++) {
        float v = tile[tx][ty + 8*i];
        __nv_bfloat16 h = __float2bfloat16(v);
        __nv_bfloat16 l = __float2bfloat16(v - __bfloat162float(h));
        size_t o = (size_t)(bx + ty + 8*i) * DIM + by + tx;
        g_wvt_h[o] = h;
        g_wvt_l[o] = l;
    }
}

// ---------------------------------------------------------------------------
// 2-stage cp.async mma.sync GEMM: C(128x128) = A@B^T over K range
// [kstart, kstart+klen). 8 warps (2m x 4n), warp tile 64x32, BK=32,
// single __syncthreads per BK tile. X3: AhBh + AlBh + AhBl.
// ---------------------------------------------------------------------------
#define PGP   40
#define TILEB (128*PGP*2)

template<bool X3>
__device__ __forceinline__ void gemm128_pipe(
    const __nv_bfloat16* __restrict__ Agh, const __nv_bfloat16* __restrict__ Agl,
    const __nv_bfloat16* __restrict__ Bgh, const __nv_bfloat16* __restrict__ Bgl,
    int row0, int col0, int kdim, int kstart, int klen,
    uint32_t sm, float acc[4][4][4])
{
    const int tid = threadIdx.x, lane = tid & 31, wid = tid >> 5;
    const int warp_m = (wid >> 2) * 64, warp_n = (wid & 3) * 32;
    const int STAGE = (X3 ? 4 : 2) * TILEB;
    const int lr = tid >> 2;
    const int lc = (tid & 3) * 8;
    const uint32_t so1 = (uint32_t)((lr * PGP + lc) * 2);
    const uint32_t so2 = (uint32_t)(((lr + 64) * PGP + lc) * 2);

    auto issue = [&](int kt, int buf) {
        uint32_t base = sm + buf * STAGE;
        const __nv_bfloat16* agh = Agh + (size_t)(row0 + lr) * kdim + kstart + kt * 32 + lc;
        const __nv_bfloat16* bgh = Bgh + (size_t)(col0 + lr) * kdim + kstart + kt * 32 + lc;
        CP16(base + so1, agh);
        CP16(base + so2, agh + 64 * kdim);
        uint32_t bb = base + (X3 ? 2 : 1) * TILEB;
        CP16(bb + so1, bgh);
        CP16(bb + so2, bgh + 64 * kdim);
        if (X3) {
            const __nv_bfloat16* agl = Agl + (size_t)(row0 + lr) * kdim + kstart + kt * 32 + lc;
            const __nv_bfloat16* bgl = Bgl + (size_t)(col0 + lr) * kdim + kstart + kt * 32 + lc;
            CP16(base + TILEB + so1, agl);
            CP16(base + TILEB + so2, agl + 64 * kdim);
            CP16(base + 3 * TILEB + so1, bgl);
            CP16(base + 3 * TILEB + so2, bgl + 64 * kdim);
        }
        CP_COMMIT();
    };

    issue(0, 0);

    const int nkt = klen / 32;
    for (int kt = 0; kt < nkt; kt++) {
        CP_WAIT0();
        __syncthreads();
        if (kt + 1 < nkt) issue(kt + 1, (kt + 1) & 1);

        const uint32_t ah_b = sm + (kt & 1) * STAGE;
        const uint32_t al_b = ah_b + TILEB;
        const uint32_t bh_b = ah_b + (X3 ? 2 : 1) * TILEB;
        const uint32_t bl_b = ah_b + 3 * TILEB;

        #pragma unroll
        for (int ks = 0; ks < 2; ks++) {
            uint32_t af[4][4], bfh[2][4];
            #pragma unroll
            for (int mt = 0; mt < 4; mt++) {
                uint32_t ad = ah_b + (uint32_t)(((warp_m + mt*16 + (lane&15))*PGP + ks*16)*2 + (lane&16));
                LDSM_X4(af[mt], ad);
            }
            #pragma unroll
            for (int p = 0; p < 2; p++) {
                uint32_t bd = bh_b + (uint32_t)(((warp_n + p*16 + (lane&7) + ((lane&16)>>1))*PGP + ks*16)*2 + ((lane&8)<<1));
                LDSM_X4(bfh[p], bd);
            }
            #pragma unroll
            for (int mt = 0; mt < 4; mt++)
                #pragma unroll
                for (int p = 0; p < 2; p++) {
                    MMA_BF16(acc[mt][2*p],   af[mt], bfh[p][0], bfh[p][1]);
                    MMA_BF16(acc[mt][2*p+1], af[mt], bfh[p][2], bfh[p][3]);
                }
            if (X3) {
                {
                    uint32_t alf[4][4];
                    #pragma unroll
                    for (int mt = 0; mt < 4; mt++) {
                        uint32_t ad = al_b + (uint32_t)(((warp_m + mt*16 + (lane&15))*PGP + ks*16)*2 + (lane&16));
                        LDSM_X4(alf[mt], ad);
                    }
                    #pragma unroll
                    for (int mt = 0; mt < 4; mt++)
                        #pragma unroll
                        for (int p = 0; p < 2; p++) {
                            MMA_BF16(acc[mt][2*p],   alf[mt], bfh[p][0], bfh[p][1]);
                            MMA_BF16(acc[mt][2*p+1], alf[mt], bfh[p][2], bfh[p][3]);
                        }
                }
                {
                    uint32_t blf[2][4];
                    #pragma unroll
                    for (int p = 0; p < 2; p++) {
                        uint32_t bd = bl_b + (uint32_t)(((warp_n + p*16 + (lane&7) + ((lane&16)>>1))*PGP + ks*16)*2 + ((lane&8)<<1));
                        LDSM_X4(blf[p], bd);
                    }
                    #pragma unroll
                    for (int mt = 0; mt < 4; mt++)
                        #pragma unroll
                        for (int p = 0; p < 2; p++) {
                            MMA_BF16(acc[mt][2*p],   af[mt], blf[p][0], blf[p][1]);
                            MMA_BF16(acc[mt][2*p+1], af[mt], blf[p][2], blf[p][3]);
                        }
                }
            }
        }
    }
}

// ---------------------------------------------------------------------------
// QKV projection (x1). grid (8, 64, 3). Q folds 0.125*log2e.
// ---------------------------------------------------------------------------
__global__ void __launch_bounds__(256, 2) proj_qkv_kernel()
{
    extern __shared__ char smraw[];
    uint32_t sm = smem_to_u32(smraw);
    const int z = blockIdx.z;
    const __nv_bfloat16* Bh = g_wh + (size_t)z * DIM * DIM;
    __nv_bfloat16* dst = (z == 0) ? g_qb : (z == 1) ? g_kb : g_vb;
    const float scale = (z == 0) ? 0.125f * LOG2E : 1.0f;
    const int row0 = blockIdx.y * 128, col0 = blockIdx.x * 128;

    float acc[4][4][4] = {};
    gemm128_pipe<false>(g_xh, nullptr, Bh, nullptr, row0, col0, DIM, 0, DIM, sm, acc);

    const int lane = threadIdx.x & 31, wid = threadIdx.x >> 5;
    const int warp_m = (wid >> 2) * 64, warp_n = (wid & 3) * 32;
    #pragma unroll
    for (int mt = 0; mt < 4; mt++) {
        int r0 = row0 + warp_m + mt*16 + (lane >> 2);
        #pragma unroll
        for (int nt = 0; nt < 4; nt++) {
            int col = col0 + warp_n + nt*8 + (lane & 3) * 2;
            int h = col >> 6, dd = col & 63;
            #pragma unroll
            for (int half = 0; half < 2; half++) {
                int r = r0 + half*8;
                int n = r >> 11, s = r & (SEQ - 1);
                __nv_bfloat162 hv = __floats2bfloat162_rn(acc[mt][nt][2*half]*scale,
                                                          acc[mt][nt][2*half+1]*scale);
                *(__nv_bfloat162*)(dst + (((size_t)(n*HEADS + h)*SEQ + s))*HD + dd) = hv;
            }
        }
    }
}

// ---------------------------------------------------------------------------
// Wvo split-K partials: grid (8, 8, 8). Each z computes K slice of 128.
// ---------------------------------------------------------------------------
__global__ void __launch_bounds__(256, 2) wvo_kernel()
{
    extern __shared__ char smraw[];
    uint32_t sm = smem_to_u32(smraw);
    const __nv_bfloat16* Ah = g_wh + (size_t)3 * DIM * DIM;
    const __nv_bfloat16* Al = g_wl + (size_t)3 * DIM * DIM;
    const int row0 = blockIdx.y * 128, col0 = blockIdx.x * 128;
    const int kstart = blockIdx.z * (DIM / WVO_SPLIT);

    float acc[4][4][4] = {};
    gemm128_pipe<true>(Ah, Al, g_wvt_h, g_wvt_l, row0, col0, DIM,
                       kstart, DIM / WVO_SPLIT, sm, acc);

    float* dst = g_wvop + (size_t)blockIdx.z * DIM * DIM;
    const int lane = threadIdx.x & 31, wid = threadIdx.x >> 5;
    const int warp_m = (wid >> 2) * 64, warp_n = (wid & 3) * 32;
    #pragma unroll
    for (int mt = 0; mt < 4; mt++) {
        int r0 = row0 + warp_m + mt*16 + (lane >> 2);
        #pragma unroll
        for (int nt = 0; nt < 4; nt++) {
            int col = col0 + warp_n + nt*8 + (lane & 3) * 2;
            #pragma unroll
            for (int half = 0; half < 2; half++) {
                int r = r0 + half*8;
                float2 f2 = {acc[mt][nt][2*half], acc[mt][nt][2*half+1]};
                *(float2*)(dst + (size_t)r * DIM + col) = f2;
            }
        }
    }
}

// Reduce split-K partials + hi/lo split. grid 1024, block 256, 4 elems/thread.
__global__ void __launch_bounds__(256) wvo_reduce_kernel()
{
    size_t i = ((size_t)blockIdx.x * 256 + threadIdx.x) * 4;
    float4 s = *(const float4*)(g_wvop + i);
    #pragma unroll
    for (int z = 1; z < WVO_SPLIT; z++) {
        float4 p = *(const float4*)(g_wvop + (size_t)z * DIM * DIM + i);
        s.x += p.x; s.y += p.y; s.z += p.z; s.w += p.w;
    }
    __nv_bfloat16 h[4], l[4];
    split4(s, h, l);
    *(uint2*)(g_wvoh + i) = *(uint2*)h;
    *(uint2*)(g_wvol + i) = *(uint2*)l;
}

// ---------------------------------------------------------------------------
// vo = X @ Wvo^T (x3). grid (8, 64). fp32 out.
// ---------------------------------------------------------------------------
__global__ void __launch_bounds__(256, 2) vo_kernel()
{
    extern __shared__ char smraw[];
    uint32_t sm = smem_to_u32(smraw);
    const int row0 = blockIdx.y * 128, col0 = blockIdx.x * 128;

    float acc[4][4][4] = {};
    gemm128_pipe<true>(g_xh, g_xl, g_wvoh, g_wvol, row0, col0, DIM, 0, DIM, sm, acc);

    const int lane = threadIdx.x & 31, wid = threadIdx.x >> 5;
    const int warp_m = (wid >> 2) * 64, warp_n = (wid & 3) * 32;
    #pragma unroll
    for (int mt = 0; mt < 4; mt++) {
        int r0 = row0 + warp_m + mt*16 + (lane >> 2);
        #pragma unroll
        for (int nt = 0; nt < 4; nt++) {
            int col = col0 + warp_n + nt*8 + (lane & 3) * 2;
            #pragma unroll
            for (int half = 0; half < 2; half++) {
                int r = r0 + half*8;
                float2 f2 = {acc[mt][nt][2*half], acc[mt][nt][2*half+1]};
                *(float2*)(g_vo + (size_t)r * DIM + col) = f2;
            }
        }
    }
}

// ---------------------------------------------------------------------------
// Output projection (x1) + bias + correction.
// ---------------------------------------------------------------------------
__global__ void __launch_bounds__(256, 2) proj_out_kernel(
    const float* __restrict__ bo, float* __restrict__ out)
{
    extern __shared__ char smraw[];
    uint32_t sm = smem_to_u32(smraw);
    const __nv_bfloat16* Bh = g_wh + (size_t)3 * DIM * DIM;
    const int row0 = blockIdx.y * 128, col0 = blockIdx.x * 128;

    float acc[4][4][4] = {};
    gemm128_pipe<false>(g_ab, nullptr, Bh, nullptr, row0, col0, DIM, 0, DIM, sm, acc);

    const int lane = threadIdx.x & 31, wid = threadIdx.x >> 5;
    const int warp_m = (wid >> 2) * 64, warp_n = (wid & 3) * 32;
    #pragma unroll
    for (int mt = 0; mt < 4; mt++) {
        int r0 = row0 + warp_m + mt*16 + (lane >> 2);
        #pragma unroll
        for (int nt = 0; nt < 4; nt++) {
            int col = col0 + warp_n + nt*8 + (lane & 3) * 2;
            float2 bb = *(const float2*)(bo + col);
            #pragma unroll
            for (int half = 0; half < 2; half++) {
                int r = r0 + half*8;
                float2 pv = *(const float2*)(g_pvo + (size_t)r * DIM + col);
                float2 f2 = {acc[mt][nt][2*half]   + bb.x + pv.x,
                             acc[mt][nt][2*half+1] + bb.y + pv.y};
                *(float2*)(out + (size_t)r * DIM + col) = f2;
            }
        }
    }
}

// ---------------------------------------------------------------------------
// Exclusive prefix of vo (two-pass), scaled by -1e9.
// ---------------------------------------------------------------------------
__global__ void __launch_bounds__(256) prefix_a_kernel()
{
    const int n = blockIdx.x, ch = blockIdx.y;
    const int d = blockIdx.z * 256 + threadIdx.x;
    const float* p = g_vo + ((size_t)(n * SEQ) + ch * 256) * DIM + d;
    float s = 0.0f;
    for (int t = 0; t < 256; t++) s += p[(size_t)t * DIM];
    g_vsum[n][ch][d] = s;
}
__global__ void __launch_bounds__(256) prefix_b_kernel()
{
    const int n = blockIdx.x, ch = blockIdx.y;
    const int d = blockIdx.z * 256 + threadIdx.x;
    float run = 0.0f;
    for (int c = 0; c < ch; c++) run += g_vsum[n][c][d];
    const float* p = g_vo  + ((size_t)(n * SEQ) + ch * 256) * DIM + d;
    float*       q = g_pvo + ((size_t)(n * SEQ) + ch * 256) * DIM + d;
    for (int t = 0; t < 256; t++) {
        q[(size_t)t * DIM] = -NEGC * run;
        run += p[(size_t)t * DIM];
    }
}

// ---------------------------------------------------------------------------
// Flash attention, 2-stage KV pipeline, fixed-shift exp2 softmax.
// grid (16, 64), 256 threads.
// ---------------------------------------------------------------------------
#define AP 72
#define AQ_BYTES (128*AP*2)
#define AKV_BYTES (64*AP*2)
#define AKV_STAGE (2*AKV_BYTES)
#define ATTN_SMEM (AQ_BYTES + 2*AKV_STAGE)

__global__ void __launch_bounds__(256, 2) attn_kernel()
{
    extern __shared__ char smraw[];
    const uint32_t sm = smem_to_u32(smraw);
    const uint32_t qs_b = sm;
    const int tid = threadIdx.x, lane = tid & 31, wid = tid >> 5;
    const int nh = blockIdx.y, q0 = blockIdx.x * 128;
    const __nv_bfloat16* qg = g_qb + (size_t)nh * SEQ * HD;
    const __nv_bfloat16* kg = g_kb + (size_t)nh * SEQ * HD;
    const __nv_bfloat16* vg = g_vb + (size_t)nh * SEQ * HD;

    const int lr = tid >> 3;
    const int lc = (tid & 7) * 8;
    const uint32_t kvo1 = (uint32_t)((lr * AP + lc) * 2);
    const uint32_t kvo2 = (uint32_t)(((lr + 32) * AP + lc) * 2);

    auto issue_kv = [&](int kt, int buf) {
        uint32_t base = sm + AQ_BYTES + buf * AKV_STAGE;
        const __nv_bfloat16* kp = kg + (size_t)(kt*64 + lr) * HD + lc;
        const __nv_bfloat16* vp = vg + (size_t)(kt*64 + lr) * HD + lc;
        CP16(base + kvo1, kp);
        CP16(base + kvo2, kp + 32 * HD);
        CP16(base + AKV_BYTES + kvo1, vp);
        CP16(base + AKV_BYTES + kvo2, vp + 32 * HD);
        CP_COMMIT();
    };

    {
        const int qr = tid >> 3, qc = (tid & 7) * 8;
        #pragma unroll
        for (int i = 0; i < 4; i++) {
            int r = qr + i * 32;
            CP16(qs_b + (uint32_t)((r * AP + qc) * 2), qg + (size_t)(q0 + r) * HD + qc);
        }
    }
    issue_kv(0, 0);

    uint32_t qf[4][4];
    const int m0 = wid * 16;
    float o[8][4] = {};
    float lr0 = 0.0f, lr1 = 0.0f;
    const int NKT = SEQ / 64;

    for (int kt = 0; kt < NKT; kt++) {
        CP_WAIT0();
        __syncthreads();
        if (kt + 1 < NKT) issue_kv(kt + 1, (kt + 1) & 1);

        if (kt == 0) {
            #pragma unroll
            for (int ks = 0; ks < 4; ks++) {
                uint32_t ad = qs_b + (uint32_t)(((m0 + (lane&15))*AP + ks*16)*2 + (lane&16));
                LDSM_X4(qf[ks], ad);
            }
        }

        const uint32_t ks_b = sm + AQ_BYTES + (kt & 1) * AKV_STAGE;
        const uint32_t vs_b = ks_b + AKV_BYTES;

        // S = Q K^T (Q pre-scaled by 0.125*log2e -> log2-domain logits)
        float sf[8][4] = {};
        #pragma unroll
        for (int ks = 0; ks < 4; ks++) {
            uint32_t bfr[4][4];
            #pragma unroll
            for (int p = 0; p < 4; p++) {
                uint32_t bd = ks_b + (uint32_t)(((p*16 + (lane&7) + ((lane&16)>>1))*AP + ks*16)*2 + ((lane&8)<<1));
                LDSM_X4(bfr[p], bd);
            }
            #pragma unroll
            for (int p = 0; p < 4; p++) {
                MMA_BF16(sf[2*p],   qf[ks], bfr[p][0], bfr[p][1]);
                MMA_BF16(sf[2*p+1], qf[ks], bfr[p][2], bfr[p][3]);
            }
        }

        // p = exp2(s' - SHIFT2) == exp(s - 8)
        uint32_t pf[4][4];
        #pragma unroll
        for (int g = 0; g < 4; g++) {
            float e00 = exp2f(sf[2*g][0]   - SHIFT2), e01 = exp2f(sf[2*g][1]   - SHIFT2);
            float e02 = exp2f(sf[2*g][2]   - SHIFT2), e03 = exp2f(sf[2*g][3]   - SHIFT2);
            float e10 = exp2f(sf[2*g+1][0] - SHIFT2), e11 = exp2f(sf[2*g+1][1] - SHIFT2);
            float e12 = exp2f(sf[2*g+1][2] - SHIFT2), e13 = exp2f(sf[2*g+1][3] - SHIFT2);
            lr0 += (e00 + e01) + (e10 + e11);
            lr1 += (e02 + e03) + (e12 + e13);
            pf[g][0] = packbf2(e00, e01);
            pf[g][1] = packbf2(e02, e03);
            pf[g][2] = packbf2(e10, e11);
            pf[g][3] = packbf2(e12, e13);
        }

        // O += P @ V
        #pragma unroll
        for (int g = 0; g < 4; g++) {
            uint32_t vf[4][4];
            #pragma unroll
            for (int p = 0; p < 4; p++) {
                uint32_t vd = vs_b + (uint32_t)(((g*16 + (lane&7) + (lane&8))*AP + p*16)*2 + (lane&16));
                LDSM_X4_T(vf[p], vd);
            }
            #pragma unroll
            for (int p = 0; p < 4; p++) {
                MMA_BF16(o[2*p],   pf[g], vf[p][0], vf[p][1]);
                MMA_BF16(o[2*p+1], pf[g], vf[p][2], vf[p][3]);
            }
        }
    }

    lr0 += __shfl_xor_sync(0xffffffffu, lr0, 1);
    lr0 += __shfl_xor_sync(0xffffffffu, lr0, 2);
    lr1 += __shfl_xor_sync(0xffffffffu, lr1, 1);
    lr1 += __shfl_xor_sync(0xffffffffu, lr1, 2);
    const float i0 = 1.0f / lr0, i1 = 1.0f / lr1;

    const int n = nh >> 4, hh = nh & 15;
    const int srow0 = q0 + m0 + (lane >> 2);
    #pragma unroll
    for (int nt = 0; nt < 8; nt++) {
        int dd = nt*8 + (lane & 3) * 2;
        #pragma unroll
        for (int half = 0; half < 2; half++) {
            int s = srow0 + half*8;
            float inv = half ? i1 : i0;
            __nv_bfloat162 hv = __floats2bfloat162_rn(o[nt][2*half] * inv,
                                                      o[nt][2*half+1] * inv);
            *(__nv_bfloat162*)(g_ab + ((size_t)(n * SEQ + s)) * DIM + hh * HD + dd) = hv;
        }
    }
}

// ---------------------------------------------------------------------------
extern "C" void kernel_launch(void* const* d_in, const int* in_sizes, int n_in,
                              void* d_out, int out_size)
{
    const float* x  = (const float*)d_in[0];
    const float* wq = (const float*)d_in[1];
    const float* wk = (const float*)d_in[2];
    const float* wv = (const float*)d_in[3];
    const float* wo = (const float*)d_in[4];
    const float* bo = (const float*)d_in[5];
    float* out = (float*)d_out;

    const int SM_X1 = 2 * 2 * TILEB;          // 40960
    const int SM_X3 = 2 * 4 * TILEB;          // 81920

    cudaFuncSetAttribute(proj_qkv_kernel,
                         cudaFuncAttributeMaxDynamicSharedMemorySize, SM_X1);
    cudaFuncSetAttribute(wvo_kernel,
                         cudaFuncAttributeMaxDynamicSharedMemorySize, SM_X3);
    cudaFuncSetAttribute(vo_kernel,
                         cudaFuncAttributeMaxDynamicSharedMemorySize, SM_X3);
    cudaFuncSetAttribute(proj_out_kernel,
                         cudaFuncAttributeMaxDynamicSharedMemorySize, SM_X1);
    cudaFuncSetAttribute(attn_kernel,
                         cudaFuncAttributeMaxDynamicSharedMemorySize, ATTN_SMEM);

    split_x_kernel<<<NS*DIM/(256*4), 256>>>(x);
    split_w_kernel<<<dim3(DIM*DIM/(256*4), 4), 256>>>(wq, wk, wv, wo);
    transpose_wv_kernel<<<dim3(32, 32), 256>>>(wv);
    wvo_kernel<<<dim3(DIM/128, DIM/128, WVO_SPLIT), 256, SM_X3>>>();
    wvo_reduce_kernel<<<DIM*DIM/(256*4), 256>>>();
    proj_qkv_kernel<<<dim3(DIM/128, NS/128, 3), 256, SM_X1>>>();
    vo_kernel<<<dim3(DIM/128, NS/128), 256, SM_X3>>>();
    prefix_a_kernel<<<dim3(NB, 8, 4), 256>>>();
    prefix_b_kernel<<<dim3(NB, 8, 4), 256>>>();
    attn_kernel<<<dim3(SEQ/128, NH), 256, ATTN_SMEM>>>();
    proj_out_kernel<<<dim3(DIM/128, NS/128), 256, SM_X1>>>(bo, out);
}

// round 10
// speedup vs baseline: 2.8748x; 2.6559x over previous
#include <cuda_runtime.h>
#include <cuda_bf16.h>
#include <cstdint>

// Problem constants
#define NB    4
#define SEQ   2048
#define DIM   1024
#define NS    (NB*SEQ)          // 8192
#define NEGC  1000000000.0f

// ---------------------------------------------------------------------------
// Scratch (device globals)
// ---------------------------------------------------------------------------
#define WVO_SPLIT 8
__device__ __align__(16) float g_vo  [(size_t)NS * DIM];                 // X @ Wvo^T
__device__ __align__(16) float g_vsum[NB][8][DIM];                       // chunk sums
__device__ __align__(16) float g_wvop[(size_t)WVO_SPLIT * DIM * DIM];    // split-K partials
__device__ __align__(16) __nv_bfloat16 g_xh[(size_t)NS * DIM];           // X hi
__device__ __align__(16) __nv_bfloat16 g_xl[(size_t)NS * DIM];           // X lo
__device__ __align__(16) __nv_bfloat16 g_woh[(size_t)DIM * DIM];         // Wo hi
__device__ __align__(16) __nv_bfloat16 g_wol[(size_t)DIM * DIM];         // Wo lo
__device__ __align__(16) __nv_bfloat16 g_wvt_h[(size_t)DIM * DIM];       // Wv^T hi
__device__ __align__(16) __nv_bfloat16 g_wvt_l[(size_t)DIM * DIM];       // Wv^T lo
__device__ __align__(16) __nv_bfloat16 g_wvoh[(size_t)DIM * DIM];        // Wvo hi
__device__ __align__(16) __nv_bfloat16 g_wvol[(size_t)DIM * DIM];        // Wvo lo

// ---------------------------------------------------------------------------
// PTX helpers
// ---------------------------------------------------------------------------
__device__ __forceinline__ uint32_t smem_to_u32(const void* p) {
    uint32_t a;
    asm("{ .reg .u64 t; cvta.to.shared.u64 t, %1; cvt.u32.u64 %0, t; }"
        : "=r"(a) : "l"(p));
    return a;
}

#define CP16(dst, src) \
    asm volatile("cp.async.cg.shared.global [%0], [%1], 16;" \
                 :: "r"((uint32_t)(dst)), "l"(src))
#define CP_COMMIT() asm volatile("cp.async.commit_group;" ::: "memory")
#define CP_WAIT0()  asm volatile("cp.async.wait_group 0;" ::: "memory")

#define LDSM_X4(r, addr) \
    asm volatile("ldmatrix.sync.aligned.m8n8.x4.shared.b16 {%0,%1,%2,%3}, [%4];" \
        : "=r"((r)[0]), "=r"((r)[1]), "=r"((r)[2]), "=r"((r)[3]) : "r"(addr))

#define MMA_BF16(c, a, b0, b1) \
    asm volatile("mma.sync.aligned.m16n8k16.row.col.f32.bf16.bf16.f32 " \
        "{%0,%1,%2,%3}, {%4,%5,%6,%7}, {%8,%9}, {%0,%1,%2,%3};" \
        : "+f"((c)[0]), "+f"((c)[1]), "+f"((c)[2]), "+f"((c)[3]) \
        : "r"((a)[0]), "r"((a)[1]), "r"((a)[2]), "r"((a)[3]), "r"(b0), "r"(b1))

// ---------------------------------------------------------------------------
// bf16 split helpers / kernels
// ---------------------------------------------------------------------------
__device__ __forceinline__ void split4(float4 v, __nv_bfloat16* h, __nv_bfloat16* l)
{
    h[0] = __float2bfloat16(v.x); l[0] = __float2bfloat16(v.x - __bfloat162float(h[0]));
    h[1] = __float2bfloat16(v.y); l[1] = __float2bfloat16(v.y - __bfloat162float(h[1]));
    h[2] = __float2bfloat16(v.z); l[2] = __float2bfloat16(v.z - __bfloat162float(h[2]));
    h[3] = __float2bfloat16(v.w); l[3] = __float2bfloat16(v.w - __bfloat162float(h[3]));
}

__global__ void __launch_bounds__(256) split_x_kernel(const float* __restrict__ x)
{
    size_t i = ((size_t)blockIdx.x * 256 + threadIdx.x) * 4;
    float4 v = *(const float4*)(x + i);
    __nv_bfloat16 h[4], l[4];
    split4(v, h, l);
    *(uint2*)(g_xh + i) = *(uint2*)h;
    *(uint2*)(g_xl + i) = *(uint2*)l;
}

__global__ void __launch_bounds__(256) split_wo_kernel(const float* __restrict__ wo)
{
    size_t i = ((size_t)blockIdx.x * 256 + threadIdx.x) * 4;
    float4 v = *(const float4*)(wo + i);
    __nv_bfloat16 h[4], l[4];
    split4(v, h, l);
    *(uint2*)(g_woh + i) = *(uint2*)h;
    *(uint2*)(g_wol + i) = *(uint2*)l;
}

// Transpose Wv (fp32 [k][j]) -> Wv^T hi/lo bf16 [j][k]
__global__ void __launch_bounds__(256) transpose_wv_kernel(const float* __restrict__ wv)
{
    __shared__ float tile[32][33];
    const int bx = blockIdx.x * 32;
    const int by = blockIdx.y * 32;
    const int tx = threadIdx.x & 31, ty = threadIdx.x >> 5;
    #pragma unroll
    for (int i = 0; i < 4; i++)
        tile[ty + 8*i][tx] = wv[(size_t)(by + ty + 8*i) * DIM + bx + tx];
    __syncthreads();
    #pragma unroll
    for (int i = 0; i < 4; i++) {
        float v = tile[tx][ty + 8*i];
        __nv_bfloat16 h = __float2bfloat16(v);
        __nv_bfloat16 l = __float2bfloat16(v - __bfloat162float(h));
        size_t o = (size_t)(bx + ty + 8*i) * DIM + by + tx;
        g_wvt_h[o] = h;
        g_wvt_l[o] = l;
    }
}

// ---------------------------------------------------------------------------
// 2-stage cp.async mma.sync x3 GEMM: C(128x128) = A@B^T over K range
// [kstart, kstart+klen). 8 warps (2m x 4n), warp tile 64x32, BK=32.
// AhBh + AlBh + AhBl, fp32 accum.
// ---------------------------------------------------------------------------
#define PGP   40
#define TILEB (128*PGP*2)
#define STAGE (4*TILEB)
#define SM_X3 (2*STAGE)      // 81920 B

__device__ __forceinline__ void gemm128_x3(
    const __nv_bfloat16* __restrict__ Agh, const __nv_bfloat16* __restrict__ Agl,
    const __nv_bfloat16* __restrict__ Bgh, const __nv_bfloat16* __restrict__ Bgl,
    int row0, int col0, int kdim, int kstart, int klen,
    uint32_t sm, float acc[4][4][4])
{
    const int tid = threadIdx.x, lane = tid & 31, wid = tid >> 5;
    const int warp_m = (wid >> 2) * 64, warp_n = (wid & 3) * 32;
    const int lr = tid >> 2;
    const int lc = (tid & 3) * 8;
    const uint32_t so1 = (uint32_t)((lr * PGP + lc) * 2);
    const uint32_t so2 = (uint32_t)(((lr + 64) * PGP + lc) * 2);

    auto issue = [&](int kt, int buf) {
        uint32_t base = sm + buf * STAGE;
        const __nv_bfloat16* agh = Agh + (size_t)(row0 + lr) * kdim + kstart + kt * 32 + lc;
        const __nv_bfloat16* agl = Agl + (size_t)(row0 + lr) * kdim + kstart + kt * 32 + lc;
        const __nv_bfloat16* bgh = Bgh + (size_t)(col0 + lr) * kdim + kstart + kt * 32 + lc;
        const __nv_bfloat16* bgl = Bgl + (size_t)(col0 + lr) * kdim + kstart + kt * 32 + lc;
        CP16(base + so1, agh);
        CP16(base + so2, agh + 64 * kdim);
        CP16(base + TILEB + so1, agl);
        CP16(base + TILEB + so2, agl + 64 * kdim);
        CP16(base + 2 * TILEB + so1, bgh);
        CP16(base + 2 * TILEB + so2, bgh + 64 * kdim);
        CP16(base + 3 * TILEB + so1, bgl);
        CP16(base + 3 * TILEB + so2, bgl + 64 * kdim);
        CP_COMMIT();
    };

    issue(0, 0);

    const int nkt = klen / 32;
    for (int kt = 0; kt < nkt; kt++) {
        CP_WAIT0();
        __syncthreads();
        if (kt + 1 < nkt) issue(kt + 1, (kt + 1) & 1);

        const uint32_t ah_b = sm + (kt & 1) * STAGE;
        const uint32_t al_b = ah_b + TILEB;
        const uint32_t bh_b = ah_b + 2 * TILEB;
        const uint32_t bl_b = ah_b + 3 * TILEB;

        #pragma unroll
        for (int ks = 0; ks < 2; ks++) {
            uint32_t af[4][4], bfh[2][4];
            #pragma unroll
            for (int mt = 0; mt < 4; mt++) {
                uint32_t ad = ah_b + (uint32_t)(((warp_m + mt*16 + (lane&15))*PGP + ks*16)*2 + (lane&16));
                LDSM_X4(af[mt], ad);
            }
            #pragma unroll
            for (int p = 0; p < 2; p++) {
                uint32_t bd = bh_b + (uint32_t)(((warp_n + p*16 + (lane&7) + ((lane&16)>>1))*PGP + ks*16)*2 + ((lane&8)<<1));
                LDSM_X4(bfh[p], bd);
            }
            #pragma unroll
            for (int mt = 0; mt < 4; mt++)
                #pragma unroll
                for (int p = 0; p < 2; p++) {
                    MMA_BF16(acc[mt][2*p],   af[mt], bfh[p][0], bfh[p][1]);
                    MMA_BF16(acc[mt][2*p+1], af[mt], bfh[p][2], bfh[p][3]);
                }
            {   // Al @ Bh
                uint32_t alf[4][4];
                #pragma unroll
                for (int mt = 0; mt < 4; mt++) {
                    uint32_t ad = al_b + (uint32_t)(((warp_m + mt*16 + (lane&15))*PGP + ks*16)*2 + (lane&16));
                    LDSM_X4(alf[mt], ad);
                }
                #pragma unroll
                for (int mt = 0; mt < 4; mt++)
                    #pragma unroll
                    for (int p = 0; p < 2; p++) {
                        MMA_BF16(acc[mt][2*p],   alf[mt], bfh[p][0], bfh[p][1]);
                        MMA_BF16(acc[mt][2*p+1], alf[mt], bfh[p][2], bfh[p][3]);
                    }
            }
            {   // Ah @ Bl
                uint32_t blf[2][4];
                #pragma unroll
                for (int p = 0; p < 2; p++) {
                    uint32_t bd = bl_b + (uint32_t)(((warp_n + p*16 + (lane&7) + ((lane&16)>>1))*PGP + ks*16)*2 + ((lane&8)<<1));
                    LDSM_X4(blf[p], bd);
                }
                #pragma unroll
                for (int mt = 0; mt < 4; mt++)
                    #pragma unroll
                    for (int p = 0; p < 2; p++) {
                        MMA_BF16(acc[mt][2*p],   af[mt], blf[p][0], blf[p][1]);
                        MMA_BF16(acc[mt][2*p+1], af[mt], blf[p][2], blf[p][3]);
                    }
            }
        }
    }
}

// ---------------------------------------------------------------------------
// Wvo split-K partials: grid (8, 8, 8). Wvo[i][j] = sum_k Wo[i][k]*Wv[k][j].
// ---------------------------------------------------------------------------
__global__ void __launch_bounds__(256, 2) wvo_kernel()
{
    extern __shared__ char smraw[];
    uint32_t sm = smem_to_u32(smraw);
    const int row0 = blockIdx.y * 128, col0 = blockIdx.x * 128;
    const int kstart = blockIdx.z * (DIM / WVO_SPLIT);

    float acc[4][4][4] = {};
    gemm128_x3(g_woh, g_wol, g_wvt_h, g_wvt_l, row0, col0, DIM,
               kstart, DIM / WVO_SPLIT, sm, acc);

    float* dst = g_wvop + (size_t)blockIdx.z * DIM * DIM;
    const int lane = threadIdx.x & 31, wid = threadIdx.x >> 5;
    const int warp_m = (wid >> 2) * 64, warp_n = (wid & 3) * 32;
    #pragma unroll
    for (int mt = 0; mt < 4; mt++) {
        int r0 = row0 + warp_m + mt*16 + (lane >> 2);
        #pragma unroll
        for (int nt = 0; nt < 4; nt++) {
            int col = col0 + warp_n + nt*8 + (lane & 3) * 2;
            #pragma unroll
            for (int half = 0; half < 2; half++) {
                int r = r0 + half*8;
                float2 f2 = {acc[mt][nt][2*half], acc[mt][nt][2*half+1]};
                *(float2*)(dst + (size_t)r * DIM + col) = f2;
            }
        }
    }
}

// Reduce split-K partials + hi/lo split.
__global__ void __launch_bounds__(256) wvo_reduce_kernel()
{
    size_t i = ((size_t)blockIdx.x * 256 + threadIdx.x) * 4;
    float4 s = *(const float4*)(g_wvop + i);
    #pragma unroll
    for (int z = 1; z < WVO_SPLIT; z++) {
        float4 p = *(const float4*)(g_wvop + (size_t)z * DIM * DIM + i);
        s.x += p.x; s.y += p.y; s.z += p.z; s.w += p.w;
    }
    __nv_bfloat16 h[4], l[4];
    split4(s, h, l);
    *(uint2*)(g_wvoh + i) = *(uint2*)h;
    *(uint2*)(g_wvol + i) = *(uint2*)l;
}

// ---------------------------------------------------------------------------
// vo = X @ Wvo^T (x3). grid (8, 64). fp32 out.
// ---------------------------------------------------------------------------
__global__ void __launch_bounds__(256, 2) vo_kernel()
{
    extern __shared__ char smraw[];
    uint32_t sm = smem_to_u32(smraw);
    const int row0 = blockIdx.y * 128, col0 = blockIdx.x * 128;

    float acc[4][4][4] = {};
    gemm128_x3(g_xh, g_xl, g_wvoh, g_wvol, row0, col0, DIM, 0, DIM, sm, acc);

    const int lane = threadIdx.x & 31, wid = threadIdx.x >> 5;
    const int warp_m = (wid >> 2) * 64, warp_n = (wid & 3) * 32;
    #pragma unroll
    for (int mt = 0; mt < 4; mt++) {
        int r0 = row0 + warp_m + mt*16 + (lane >> 2);
        #pragma unroll
        for (int nt = 0; nt < 4; nt++) {
            int col = col0 + warp_n + nt*8 + (lane & 3) * 2;
            #pragma unroll
            for (int half = 0; half < 2; half++) {
                int r = r0 + half*8;
                float2 f2 = {acc[mt][nt][2*half], acc[mt][nt][2*half+1]};
                *(float2*)(g_vo + (size_t)r * DIM + col) = f2;
            }
        }
    }
}

// ---------------------------------------------------------------------------
// Prefix pass A: per-(batch, 256-row chunk, d) partial sums of vo.
// grid (NB, 8, 4), block 256.
// ---------------------------------------------------------------------------
__global__ void __launch_bounds__(256) prefix_a_kernel()
{
    const int n = blockIdx.x, ch = blockIdx.y;
    const int d = blockIdx.z * 256 + threadIdx.x;
    const float* p = g_vo + ((size_t)(n * SEQ) + ch * 256) * DIM + d;
    float s = 0.0f;
    for (int t = 0; t < 256; t++) s += p[(size_t)t * DIM];
    g_vsum[n][ch][d] = s;
}

// ---------------------------------------------------------------------------
// Prefix pass B fused with output:  out[n,s,d] = bo[d] - 1e9 * prefix(vo)[n,s,d]
// (exclusive prefix over s). grid (NB, 8, 4), block 256.
// ---------------------------------------------------------------------------
__global__ void __launch_bounds__(256) prefix_out_kernel(
    const float* __restrict__ bo, float* __restrict__ out)
{
    const int n = blockIdx.x, ch = blockIdx.y;
    const int d = blockIdx.z * 256 + threadIdx.x;
    float run = 0.0f;
    for (int c = 0; c < ch; c++) run += g_vsum[n][c][d];
    const float b = bo[d];
    const float* p = g_vo + ((size_t)(n * SEQ) + ch * 256) * DIM + d;
    float*       q = out  + ((size_t)(n * SEQ) + ch * 256) * DIM + d;
    for (int t = 0; t < 256; t++) {
        q[(size_t)t * DIM] = b - NEGC * run;
        run += p[(size_t)t * DIM];
    }
}

// ---------------------------------------------------------------------------
extern "C" void kernel_launch(void* const* d_in, const int* in_sizes, int n_in,
                              void* d_out, int out_size)
{
    const float* x  = (const float*)d_in[0];
    const float* wv = (const float*)d_in[3];
    const float* wo = (const float*)d_in[4];
    const float* bo = (const float*)d_in[5];
    float* out = (float*)d_out;

    cudaFuncSetAttribute(wvo_kernel,
                         cudaFuncAttributeMaxDynamicSharedMemorySize, SM_X3);
    cudaFuncSetAttribute(vo_kernel,
                         cudaFuncAttributeMaxDynamicSharedMemorySize, SM_X3);

    split_x_kernel<<<NS*DIM/(256*4), 256>>>(x);
    split_wo_kernel<<<DIM*DIM/(256*4), 256>>>(wo);
    transpose_wv_kernel<<<dim3(32, 32), 256>>>(wv);
    wvo_kernel<<<dim3(DIM/128, DIM/128, WVO_SPLIT), 256, SM_X3>>>();
    wvo_reduce_kernel<<<DIM*DIM/(256*4), 256>>>();
    vo_kernel<<<dim3(DIM/128, NS/128), 256, SM_X3>>>();
    prefix_a_kernel<<<dim3(NB, 8, 4), 256>>>();
    prefix_out_kernel<<<dim3(NB, 8, 4), 256>>>(bo, out);
}

// round 11
// speedup vs baseline: 3.4379x; 1.1959x over previous
#include <cuda_runtime.h>
#include <cuda_bf16.h>
#include <cstdint>

// Problem constants
#define NB    4
#define SEQ   2048
#define DIM   1024
#define NS    (NB*SEQ)          // 8192
#define NEGC  1000000000.0f

// ---------------------------------------------------------------------------
// Scratch (device globals)
// ---------------------------------------------------------------------------
#define WVO_SPLIT 8
__device__ __align__(16) float g_xsum[NB][8][DIM];                       // chunk sums of x
__device__ __align__(16) float g_wvop[(size_t)WVO_SPLIT * DIM * DIM];    // split-K partials
__device__ __align__(16) __nv_bfloat16 g_pxh[(size_t)NS * DIM];          // prefix(X) hi
__device__ __align__(16) __nv_bfloat16 g_pxl[(size_t)NS * DIM];          // prefix(X) lo
__device__ __align__(16) __nv_bfloat16 g_woh[(size_t)DIM * DIM];         // Wo hi
__device__ __align__(16) __nv_bfloat16 g_wol[(size_t)DIM * DIM];         // Wo lo
__device__ __align__(16) __nv_bfloat16 g_wvt_h[(size_t)DIM * DIM];       // Wv^T hi
__device__ __align__(16) __nv_bfloat16 g_wvt_l[(size_t)DIM * DIM];       // Wv^T lo
__device__ __align__(16) __nv_bfloat16 g_wvoh[(size_t)DIM * DIM];        // Wvo hi
__device__ __align__(16) __nv_bfloat16 g_wvol[(size_t)DIM * DIM];        // Wvo lo

// ---------------------------------------------------------------------------
// PTX helpers
// ---------------------------------------------------------------------------
__device__ __forceinline__ uint32_t smem_to_u32(const void* p) {
    uint32_t a;
    asm("{ .reg .u64 t; cvta.to.shared.u64 t, %1; cvt.u32.u64 %0, t; }"
        : "=r"(a) : "l"(p));
    return a;
}

#define CP16(dst, src) \
    asm volatile("cp.async.cg.shared.global [%0], [%1], 16;" \
                 :: "r"((uint32_t)(dst)), "l"(src))
#define CP_COMMIT() asm volatile("cp.async.commit_group;" ::: "memory")
#define CP_WAIT0()  asm volatile("cp.async.wait_group 0;" ::: "memory")

#define LDSM_X4(r, addr) \
    asm volatile("ldmatrix.sync.aligned.m8n8.x4.shared.b16 {%0,%1,%2,%3}, [%4];" \
        : "=r"((r)[0]), "=r"((r)[1]), "=r"((r)[2]), "=r"((r)[3]) : "r"(addr))

#define MMA_BF16(c, a, b0, b1) \
    asm volatile("mma.sync.aligned.m16n8k16.row.col.f32.bf16.bf16.f32 " \
        "{%0,%1,%2,%3}, {%4,%5,%6,%7}, {%8,%9}, {%0,%1,%2,%3};" \
        : "+f"((c)[0]), "+f"((c)[1]), "+f"((c)[2]), "+f"((c)[3]) \
        : "r"((a)[0]), "r"((a)[1]), "r"((a)[2]), "r"((a)[3]), "r"(b0), "r"(b1))

// ---------------------------------------------------------------------------
// bf16 split helpers / kernels
// ---------------------------------------------------------------------------
__device__ __forceinline__ void split4(float4 v, __nv_bfloat16* h, __nv_bfloat16* l)
{
    h[0] = __float2bfloat16(v.x); l[0] = __float2bfloat16(v.x - __bfloat162float(h[0]));
    h[1] = __float2bfloat16(v.y); l[1] = __float2bfloat16(v.y - __bfloat162float(h[1]));
    h[2] = __float2bfloat16(v.z); l[2] = __float2bfloat16(v.z - __bfloat162float(h[2]));
    h[3] = __float2bfloat16(v.w); l[3] = __float2bfloat16(v.w - __bfloat162float(h[3]));
}

__global__ void __launch_bounds__(256) split_wo_kernel(const float* __restrict__ wo)
{
    size_t i = ((size_t)blockIdx.x * 256 + threadIdx.x) * 4;
    float4 v = *(const float4*)(wo + i);
    __nv_bfloat16 h[4], l[4];
    split4(v, h, l);
    *(uint2*)(g_woh + i) = *(uint2*)h;
    *(uint2*)(g_wol + i) = *(uint2*)l;
}

// Transpose Wv (fp32 [k][j]) -> Wv^T hi/lo bf16 [j][k]
__global__ void __launch_bounds__(256) transpose_wv_kernel(const float* __restrict__ wv)
{
    __shared__ float tile[32][33];
    const int bx = blockIdx.x * 32;
    const int by = blockIdx.y * 32;
    const int tx = threadIdx.x & 31, ty = threadIdx.x >> 5;
    #pragma unroll
    for (int i = 0; i < 4; i++)
        tile[ty + 8*i][tx] = wv[(size_t)(by + ty + 8*i) * DIM + bx + tx];
    __syncthreads();
    #pragma unroll
    for (int i = 0; i < 4; i++) {
        float v = tile[tx][ty + 8*i];
        __nv_bfloat16 h = __float2bfloat16(v);
        __nv_bfloat16 l = __float2bfloat16(v - __bfloat162float(h));
        size_t o = (size_t)(bx + ty + 8*i) * DIM + by + tx;
        g_wvt_h[o] = h;
        g_wvt_l[o] = l;
    }
}

// ---------------------------------------------------------------------------
// Prefix of X, pass A: per-(batch, 256-row chunk, d) partial sums.
// grid (NB, 8, 4), block 256.
// ---------------------------------------------------------------------------
__global__ void __launch_bounds__(256) prefix_x_a_kernel(const float* __restrict__ x)
{
    const int n = blockIdx.x, ch = blockIdx.y;
    const int d = blockIdx.z * 256 + threadIdx.x;
    const float* p = x + ((size_t)(n * SEQ) + ch * 256) * DIM + d;
    float s = 0.0f;
    for (int t = 0; t < 256; t++) s += p[(size_t)t * DIM];
    g_xsum[n][ch][d] = s;
}

// Pass B: exclusive prefix of X, written as bf16 hi/lo. grid (NB, 8, 4).
__global__ void __launch_bounds__(256) prefix_x_b_kernel(const float* __restrict__ x)
{
    const int n = blockIdx.x, ch = blockIdx.y;
    const int d = blockIdx.z * 256 + threadIdx.x;
    float run = 0.0f;
    for (int c = 0; c < ch; c++) run += g_xsum[n][c][d];
    const float* p = x + ((size_t)(n * SEQ) + ch * 256) * DIM + d;
    size_t o = ((size_t)(n * SEQ) + ch * 256) * DIM + d;
    for (int t = 0; t < 256; t++) {
        __nv_bfloat16 h = __float2bfloat16(run);
        __nv_bfloat16 l = __float2bfloat16(run - __bfloat162float(h));
        g_pxh[o] = h;
        g_pxl[o] = l;
        run += p[(size_t)t * DIM];
        o += DIM;
    }
}

// ---------------------------------------------------------------------------
// 2-stage cp.async mma.sync x3 GEMM: C(128x128) = A@B^T over K range
// [kstart, kstart+klen). 8 warps (2m x 4n), warp tile 64x32, BK=32.
// AhBh + AlBh + AhBl, fp32 accum.
// ---------------------------------------------------------------------------
#define PGP   40
#define TILEB (128*PGP*2)
#define STAGE (4*TILEB)
#define SM_X3 (2*STAGE)      // 81920 B

__device__ __forceinline__ void gemm128_x3(
    const __nv_bfloat16* __restrict__ Agh, const __nv_bfloat16* __restrict__ Agl,
    const __nv_bfloat16* __restrict__ Bgh, const __nv_bfloat16* __restrict__ Bgl,
    int row0, int col0, int kdim, int kstart, int klen,
    uint32_t sm, float acc[4][4][4])
{
    const int tid = threadIdx.x, lane = tid & 31, wid = tid >> 5;
    const int warp_m = (wid >> 2) * 64, warp_n = (wid & 3) * 32;
    const int lr = tid >> 2;
    const int lc = (tid & 3) * 8;
    const uint32_t so1 = (uint32_t)((lr * PGP + lc) * 2);
    const uint32_t so2 = (uint32_t)(((lr + 64) * PGP + lc) * 2);

    auto issue = [&](int kt, int buf) {
        uint32_t base = sm + buf * STAGE;
        const __nv_bfloat16* agh = Agh + (size_t)(row0 + lr) * kdim + kstart + kt * 32 + lc;
        const __nv_bfloat16* agl = Agl + (size_t)(row0 + lr) * kdim + kstart + kt * 32 + lc;
        const __nv_bfloat16* bgh = Bgh + (size_t)(col0 + lr) * kdim + kstart + kt * 32 + lc;
        const __nv_bfloat16* bgl = Bgl + (size_t)(col0 + lr) * kdim + kstart + kt * 32 + lc;
        CP16(base + so1, agh);
        CP16(base + so2, agh + 64 * kdim);
        CP16(base + TILEB + so1, agl);
        CP16(base + TILEB + so2, agl + 64 * kdim);
        CP16(base + 2 * TILEB + so1, bgh);
        CP16(base + 2 * TILEB + so2, bgh + 64 * kdim);
        CP16(base + 3 * TILEB + so1, bgl);
        CP16(base + 3 * TILEB + so2, bgl + 64 * kdim);
        CP_COMMIT();
    };

    issue(0, 0);

    const int nkt = klen / 32;
    for (int kt = 0; kt < nkt; kt++) {
        CP_WAIT0();
        __syncthreads();
        if (kt + 1 < nkt) issue(kt + 1, (kt + 1) & 1);

        const uint32_t ah_b = sm + (kt & 1) * STAGE;
        const uint32_t al_b = ah_b + TILEB;
        const uint32_t bh_b = ah_b + 2 * TILEB;
        const uint32_t bl_b = ah_b + 3 * TILEB;

        #pragma unroll
        for (int ks = 0; ks < 2; ks++) {
            uint32_t af[4][4], bfh[2][4];
            #pragma unroll
            for (int mt = 0; mt < 4; mt++) {
                uint32_t ad = ah_b + (uint32_t)(((warp_m + mt*16 + (lane&15))*PGP + ks*16)*2 + (lane&16));
                LDSM_X4(af[mt], ad);
            }
            #pragma unroll
            for (int p = 0; p < 2; p++) {
                uint32_t bd = bh_b + (uint32_t)(((warp_n + p*16 + (lane&7) + ((lane&16)>>1))*PGP + ks*16)*2 + ((lane&8)<<1));
                LDSM_X4(bfh[p], bd);
            }
            #pragma unroll
            for (int mt = 0; mt < 4; mt++)
                #pragma unroll
                for (int p = 0; p < 2; p++) {
                    MMA_BF16(acc[mt][2*p],   af[mt], bfh[p][0], bfh[p][1]);
                    MMA_BF16(acc[mt][2*p+1], af[mt], bfh[p][2], bfh[p][3]);
                }
            {   // Al @ Bh
                uint32_t alf[4][4];
                #pragma unroll
                for (int mt = 0; mt < 4; mt++) {
                    uint32_t ad = al_b + (uint32_t)(((warp_m + mt*16 + (lane&15))*PGP + ks*16)*2 + (lane&16));
                    LDSM_X4(alf[mt], ad);
                }
                #pragma unroll
                for (int mt = 0; mt < 4; mt++)
                    #pragma unroll
                    for (int p = 0; p < 2; p++) {
                        MMA_BF16(acc[mt][2*p],   alf[mt], bfh[p][0], bfh[p][1]);
                        MMA_BF16(acc[mt][2*p+1], alf[mt], bfh[p][2], bfh[p][3]);
                    }
            }
            {   // Ah @ Bl
                uint32_t blf[2][4];
                #pragma unroll
                for (int p = 0; p < 2; p++) {
                    uint32_t bd = bl_b + (uint32_t)(((warp_n + p*16 + (lane&7) + ((lane&16)>>1))*PGP + ks*16)*2 + ((lane&8)<<1));
                    LDSM_X4(blf[p], bd);
                }
                #pragma unroll
                for (int mt = 0; mt < 4; mt++)
                    #pragma unroll
                    for (int p = 0; p < 2; p++) {
                        MMA_BF16(acc[mt][2*p],   af[mt], blf[p][0], blf[p][1]);
                        MMA_BF16(acc[mt][2*p+1], af[mt], blf[p][2], blf[p][3]);
                    }
            }
        }
    }
}

// ---------------------------------------------------------------------------
// Wvo split-K partials: grid (8, 8, 8). Wvo[i][j] = sum_k Wo[i][k]*Wv[k][j].
// ---------------------------------------------------------------------------
__global__ void __launch_bounds__(256, 2) wvo_kernel()
{
    extern __shared__ char smraw[];
    uint32_t sm = smem_to_u32(smraw);
    const int row0 = blockIdx.y * 128, col0 = blockIdx.x * 128;
    const int kstart = blockIdx.z * (DIM / WVO_SPLIT);

    float acc[4][4][4] = {};
    gemm128_x3(g_woh, g_wol, g_wvt_h, g_wvt_l, row0, col0, DIM,
               kstart, DIM / WVO_SPLIT, sm, acc);

    float* dst = g_wvop + (size_t)blockIdx.z * DIM * DIM;
    const int lane = threadIdx.x & 31, wid = threadIdx.x >> 5;
    const int warp_m = (wid >> 2) * 64, warp_n = (wid & 3) * 32;
    #pragma unroll
    for (int mt = 0; mt < 4; mt++) {
        int r0 = row0 + warp_m + mt*16 + (lane >> 2);
        #pragma unroll
        for (int nt = 0; nt < 4; nt++) {
            int col = col0 + warp_n + nt*8 + (lane & 3) * 2;
            #pragma unroll
            for (int half = 0; half < 2; half++) {
                int r = r0 + half*8;
                float2 f2 = {acc[mt][nt][2*half], acc[mt][nt][2*half+1]};
                *(float2*)(dst + (size_t)r * DIM + col) = f2;
            }
        }
    }
}

// Reduce split-K partials + hi/lo split.
__global__ void __launch_bounds__(256) wvo_reduce_kernel()
{
    size_t i = ((size_t)blockIdx.x * 256 + threadIdx.x) * 4;
    float4 s = *(const float4*)(g_wvop + i);
    #pragma unroll
    for (int z = 1; z < WVO_SPLIT; z++) {
        float4 p = *(const float4*)(g_wvop + (size_t)z * DIM * DIM + i);
        s.x += p.x; s.y += p.y; s.z += p.z; s.w += p.w;
    }
    __nv_bfloat16 h[4], l[4];
    split4(s, h, l);
    *(uint2*)(g_wvoh + i) = *(uint2*)h;
    *(uint2*)(g_wvol + i) = *(uint2*)l;
}

// ---------------------------------------------------------------------------
// cum = prefix(X) @ Wvo^T (x3); epilogue writes out = bo - 1e9*cum directly.
// grid (8, 64), block 256.
// ---------------------------------------------------------------------------
__global__ void __launch_bounds__(256, 2) cum_out_kernel(
    const float* __restrict__ bo, float* __restrict__ out)
{
    extern __shared__ char smraw[];
    uint32_t sm = smem_to_u32(smraw);
    const int row0 = blockIdx.y * 128, col0 = blockIdx.x * 128;

    float acc[4][4][4] = {};
    gemm128_x3(g_pxh, g_pxl, g_wvoh, g_wvol, row0, col0, DIM, 0, DIM, sm, acc);

    const int lane = threadIdx.x & 31, wid = threadIdx.x >> 5;
    const int warp_m = (wid >> 2) * 64, warp_n = (wid & 3) * 32;
    #pragma unroll
    for (int mt = 0; mt < 4; mt++) {
        int r0 = row0 + warp_m + mt*16 + (lane >> 2);
        #pragma unroll
        for (int nt = 0; nt < 4; nt++) {
            int col = col0 + warp_n + nt*8 + (lane & 3) * 2;
            float2 bb = *(const float2*)(bo + col);
            #pragma unroll
            for (int half = 0; half < 2; half++) {
                int r = r0 + half*8;
                float2 f2 = {bb.x - NEGC * acc[mt][nt][2*half],
                             bb.y - NEGC * acc[mt][nt][2*half+1]};
                *(float2*)(out + (size_t)r * DIM + col) = f2;
            }
        }
    }
}

// ---------------------------------------------------------------------------
extern "C" void kernel_launch(void* const* d_in, const int* in_sizes, int n_in,
                              void* d_out, int out_size)
{
    const float* x  = (const float*)d_in[0];
    const float* wv = (const float*)d_in[3];
    const float* wo = (const float*)d_in[4];
    const float* bo = (const float*)d_in[5];
    float* out = (float*)d_out;

    cudaFuncSetAttribute(wvo_kernel,
                         cudaFuncAttributeMaxDynamicSharedMemorySize, SM_X3);
    cudaFuncSetAttribute(cum_out_kernel,
                         cudaFuncAttributeMaxDynamicSharedMemorySize, SM_X3);

    split_wo_kernel<<<DIM*DIM/(256*4), 256>>>(wo);
    transpose_wv_kernel<<<dim3(32, 32), 256>>>(wv);
    prefix_x_a_kernel<<<dim3(NB, 8, 4), 256>>>(x);
    prefix_x_b_kernel<<<dim3(NB, 8, 4), 256>>>(x);
    wvo_kernel<<<dim3(DIM/128, DIM/128, WVO_SPLIT), 256, SM_X3>>>();
    wvo_reduce_kernel<<<DIM*DIM/(256*4), 256>>>();
    cum_out_kernel<<<dim3(DIM/128, NS/128), 256, SM_X3>>>(bo, out);
}

// round 12
// speedup vs baseline: 4.4863x; 1.3050x over previous
#include <cuda_runtime.h>
#include <cuda_bf16.h>
#include <cuda_fp16.h>
#include <cstdint>

// Problem constants
#define NB    4
#define SEQ   2048
#define DIM   1024
#define NS    (NB*SEQ)          // 8192
#define NEGC  1000000000.0f
#define NCH   32                // prefix chunks per batch
#define CHR   (SEQ/NCH)         // 64 rows per chunk

// ---------------------------------------------------------------------------
// Scratch (device globals)
// ---------------------------------------------------------------------------
#define WVO_SPLIT 8
__device__ __align__(16) float g_xsum[NB][NCH][DIM];                     // chunk sums of x
__device__ __align__(16) float g_wvop[(size_t)WVO_SPLIT * DIM * DIM];    // split-K partials
__device__ __align__(16) __half g_pxh[(size_t)NS * DIM];                 // prefix(X) hi fp16
__device__ __align__(16) __half g_pxl[(size_t)NS * DIM];                 // prefix(X) lo fp16
__device__ __align__(16) __half g_wvoh[(size_t)DIM * DIM];               // Wvo fp16
__device__ __align__(16) __nv_bfloat16 g_woh[(size_t)DIM * DIM];         // Wo hi bf16
__device__ __align__(16) __nv_bfloat16 g_wol[(size_t)DIM * DIM];         // Wo lo bf16
__device__ __align__(16) __nv_bfloat16 g_wvt_h[(size_t)DIM * DIM];       // Wv^T hi
__device__ __align__(16) __nv_bfloat16 g_wvt_l[(size_t)DIM * DIM];       // Wv^T lo

// ---------------------------------------------------------------------------
// PTX helpers
// ---------------------------------------------------------------------------
__device__ __forceinline__ uint32_t smem_to_u32(const void* p) {
    uint32_t a;
    asm("{ .reg .u64 t; cvta.to.shared.u64 t, %1; cvt.u32.u64 %0, t; }"
        : "=r"(a) : "l"(p));
    return a;
}

#define CP16(dst, src) \
    asm volatile("cp.async.cg.shared.global [%0], [%1], 16;" \
                 :: "r"((uint32_t)(dst)), "l"(src))
#define CP_COMMIT() asm volatile("cp.async.commit_group;" ::: "memory")
#define CP_WAIT0()  asm volatile("cp.async.wait_group 0;" ::: "memory")

#define LDSM_X4(r, addr) \
    asm volatile("ldmatrix.sync.aligned.m8n8.x4.shared.b16 {%0,%1,%2,%3}, [%4];" \
        : "=r"((r)[0]), "=r"((r)[1]), "=r"((r)[2]), "=r"((r)[3]) : "r"(addr))

#define MMA_BF16(c, a, b0, b1) \
    asm volatile("mma.sync.aligned.m16n8k16.row.col.f32.bf16.bf16.f32 " \
        "{%0,%1,%2,%3}, {%4,%5,%6,%7}, {%8,%9}, {%0,%1,%2,%3};" \
        : "+f"((c)[0]), "+f"((c)[1]), "+f"((c)[2]), "+f"((c)[3]) \
        : "r"((a)[0]), "r"((a)[1]), "r"((a)[2]), "r"((a)[3]), "r"(b0), "r"(b1))

#define MMA_F16(c, a, b0, b1) \
    asm volatile("mma.sync.aligned.m16n8k16.row.col.f32.f16.f16.f32 " \
        "{%0,%1,%2,%3}, {%4,%5,%6,%7}, {%8,%9}, {%0,%1,%2,%3};" \
        : "+f"((c)[0]), "+f"((c)[1]), "+f"((c)[2]), "+f"((c)[3]) \
        : "r"((a)[0]), "r"((a)[1]), "r"((a)[2]), "r"((a)[3]), "r"(b0), "r"(b1))

// ---------------------------------------------------------------------------
// split helpers / prep kernels
// ---------------------------------------------------------------------------
__device__ __forceinline__ void split4bf(float4 v, __nv_bfloat16* h, __nv_bfloat16* l)
{
    h[0] = __float2bfloat16(v.x); l[0] = __float2bfloat16(v.x - __bfloat162float(h[0]));
    h[1] = __float2bfloat16(v.y); l[1] = __float2bfloat16(v.y - __bfloat162float(h[1]));
    h[2] = __float2bfloat16(v.z); l[2] = __float2bfloat16(v.z - __bfloat162float(h[2]));
    h[3] = __float2bfloat16(v.w); l[3] = __float2bfloat16(v.w - __bfloat162float(h[3]));
}

__global__ void __launch_bounds__(256) split_wo_kernel(const float* __restrict__ wo)
{
    size_t i = ((size_t)blockIdx.x * 256 + threadIdx.x) * 4;
    float4 v = *(const float4*)(wo + i);
    __nv_bfloat16 h[4], l[4];
    split4bf(v, h, l);
    *(uint2*)(g_woh + i) = *(uint2*)h;
    *(uint2*)(g_wol + i) = *(uint2*)l;
}

// Transpose Wv (fp32 [k][j]) -> Wv^T hi/lo bf16 [j][k]
__global__ void __launch_bounds__(256) transpose_wv_kernel(const float* __restrict__ wv)
{
    __shared__ float tile[32][33];
    const int bx = blockIdx.x * 32;
    const int by = blockIdx.y * 32;
    const int tx = threadIdx.x & 31, ty = threadIdx.x >> 5;
    #pragma unroll
    for (int i = 0; i < 4; i++)
        tile[ty + 8*i][tx] = wv[(size_t)(by + ty + 8*i) * DIM + bx + tx];
    __syncthreads();
    #pragma unroll
    for (int i = 0; i < 4; i++) {
        float v = tile[tx][ty + 8*i];
        __nv_bfloat16 h = __float2bfloat16(v);
        __nv_bfloat16 l = __float2bfloat16(v - __bfloat162float(h));
        size_t o = (size_t)(bx + ty + 8*i) * DIM + by + tx;
        g_wvt_h[o] = h;
        g_wvt_l[o] = l;
    }
}

// ---------------------------------------------------------------------------
// Prefix of X, pass A: per-(batch, 64-row chunk, d) partial sums.
// grid (NB, NCH, 4), block 256.
// ---------------------------------------------------------------------------
__global__ void __launch_bounds__(256) prefix_x_a_kernel(const float* __restrict__ x)
{
    const int n = blockIdx.x, ch = blockIdx.y;
    const int d = blockIdx.z * 256 + threadIdx.x;
    const float* p = x + ((size_t)(n * SEQ) + ch * CHR) * DIM + d;
    float s = 0.0f;
    for (int t = 0; t < CHR; t++) s += p[(size_t)t * DIM];
    g_xsum[n][ch][d] = s;
}

// Pass B: exclusive prefix of X, written as fp16 hi/lo. grid (NB, NCH, 4).
__global__ void __launch_bounds__(256) prefix_x_b_kernel(const float* __restrict__ x)
{
    const int n = blockIdx.x, ch = blockIdx.y;
    const int d = blockIdx.z * 256 + threadIdx.x;
    float run = 0.0f;
    for (int c = 0; c < ch; c++) run += g_xsum[n][c][d];
    const float* p = x + ((size_t)(n * SEQ) + ch * CHR) * DIM + d;
    size_t o = ((size_t)(n * SEQ) + ch * CHR) * DIM + d;
    for (int t = 0; t < CHR; t++) {
        __half h = __float2half_rn(run);
        __half l = __float2half_rn(run - __half2float(h));
        g_pxh[o] = h;
        g_pxl[o] = l;
        run += p[(size_t)t * DIM];
        o += DIM;
    }
}

// ---------------------------------------------------------------------------
// Shared GEMM geometry
// ---------------------------------------------------------------------------
#define PGP   40
#define TILEB (128*PGP*2)
#define STAGE3 (4*TILEB)
#define SM_X3 (2*STAGE3)     // 81920 B  (bf16 x3: Ah Al Bh Bl)
#define STAGE2 (3*TILEB)
#define SM_X2 (2*STAGE2)     // 61440 B  (fp16 x2: Ah Al Bh)

// ---------------------------------------------------------------------------
// bf16 x3 GEMM (AhBh + AlBh + AhBl) over K range. Used for Wvo only.
// ---------------------------------------------------------------------------
__device__ __forceinline__ void gemm128_x3(
    const __nv_bfloat16* __restrict__ Agh, const __nv_bfloat16* __restrict__ Agl,
    const __nv_bfloat16* __restrict__ Bgh, const __nv_bfloat16* __restrict__ Bgl,
    int row0, int col0, int kdim, int kstart, int klen,
    uint32_t sm, float acc[4][4][4])
{
    const int tid = threadIdx.x, lane = tid & 31, wid = tid >> 5;
    const int warp_m = (wid >> 2) * 64, warp_n = (wid & 3) * 32;
    const int lr = tid >> 2;
    const int lc = (tid & 3) * 8;
    const uint32_t so1 = (uint32_t)((lr * PGP + lc) * 2);
    const uint32_t so2 = (uint32_t)(((lr + 64) * PGP + lc) * 2);

    auto issue = [&](int kt, int buf) {
        uint32_t base = sm + buf * STAGE3;
        const __nv_bfloat16* agh = Agh + (size_t)(row0 + lr) * kdim + kstart + kt * 32 + lc;
        const __nv_bfloat16* agl = Agl + (size_t)(row0 + lr) * kdim + kstart + kt * 32 + lc;
        const __nv_bfloat16* bgh = Bgh + (size_t)(col0 + lr) * kdim + kstart + kt * 32 + lc;
        const __nv_bfloat16* bgl = Bgl + (size_t)(col0 + lr) * kdim + kstart + kt * 32 + lc;
        CP16(base + so1, agh);
        CP16(base + so2, agh + 64 * kdim);
        CP16(base + TILEB + so1, agl);
        CP16(base + TILEB + so2, agl + 64 * kdim);
        CP16(base + 2 * TILEB + so1, bgh);
        CP16(base + 2 * TILEB + so2, bgh + 64 * kdim);
        CP16(base + 3 * TILEB + so1, bgl);
        CP16(base + 3 * TILEB + so2, bgl + 64 * kdim);
        CP_COMMIT();
    };

    issue(0, 0);
    const int nkt = klen / 32;
    for (int kt = 0; kt < nkt; kt++) {
        CP_WAIT0();
        __syncthreads();
        if (kt + 1 < nkt) issue(kt + 1, (kt + 1) & 1);

        const uint32_t ah_b = sm + (kt & 1) * STAGE3;
        const uint32_t al_b = ah_b + TILEB;
        const uint32_t bh_b = ah_b + 2 * TILEB;
        const uint32_t bl_b = ah_b + 3 * TILEB;

        #pragma unroll
        for (int ks = 0; ks < 2; ks++) {
            uint32_t af[4][4], bfh[2][4];
            #pragma unroll
            for (int mt = 0; mt < 4; mt++) {
                uint32_t ad = ah_b + (uint32_t)(((warp_m + mt*16 + (lane&15))*PGP + ks*16)*2 + (lane&16));
                LDSM_X4(af[mt], ad);
            }
            #pragma unroll
            for (int p = 0; p < 2; p++) {
                uint32_t bd = bh_b + (uint32_t)(((warp_n + p*16 + (lane&7) + ((lane&16)>>1))*PGP + ks*16)*2 + ((lane&8)<<1));
                LDSM_X4(bfh[p], bd);
            }
            #pragma unroll
            for (int mt = 0; mt < 4; mt++)
                #pragma unroll
                for (int p = 0; p < 2; p++) {
                    MMA_BF16(acc[mt][2*p],   af[mt], bfh[p][0], bfh[p][1]);
                    MMA_BF16(acc[mt][2*p+1], af[mt], bfh[p][2], bfh[p][3]);
                }
            {   // Al @ Bh
                uint32_t alf[4][4];
                #pragma unroll
                for (int mt = 0; mt < 4; mt++) {
                    uint32_t ad = al_b + (uint32_t)(((warp_m + mt*16 + (lane&15))*PGP + ks*16)*2 + (lane&16));
                    LDSM_X4(alf[mt], ad);
                }
                #pragma unroll
                for (int mt = 0; mt < 4; mt++)
                    #pragma unroll
                    for (int p = 0; p < 2; p++) {
                        MMA_BF16(acc[mt][2*p],   alf[mt], bfh[p][0], bfh[p][1]);
                        MMA_BF16(acc[mt][2*p+1], alf[mt], bfh[p][2], bfh[p][3]);
                    }
            }
            {   // Ah @ Bl
                uint32_t blf[2][4];
                #pragma unroll
                for (int p = 0; p < 2; p++) {
                    uint32_t bd = bl_b + (uint32_t)(((warp_n + p*16 + (lane&7) + ((lane&16)>>1))*PGP + ks*16)*2 + ((lane&8)<<1));
                    LDSM_X4(blf[p], bd);
                }
                #pragma unroll
                for (int mt = 0; mt < 4; mt++)
                    #pragma unroll
                    for (int p = 0; p < 2; p++) {
                        MMA_BF16(acc[mt][2*p],   af[mt], blf[p][0], blf[p][1]);
                        MMA_BF16(acc[mt][2*p+1], af[mt], blf[p][2], blf[p][3]);
                    }
            }
        }
    }
}

// ---------------------------------------------------------------------------
// Wvo split-K partials (bf16 x3): grid (8, 8, 8).
// ---------------------------------------------------------------------------
__global__ void __launch_bounds__(256, 2) wvo_kernel()
{
    extern __shared__ char smraw[];
    uint32_t sm = smem_to_u32(smraw);
    const int row0 = blockIdx.y * 128, col0 = blockIdx.x * 128;
    const int kstart = blockIdx.z * (DIM / WVO_SPLIT);

    float acc[4][4][4] = {};
    gemm128_x3(g_woh, g_wol, g_wvt_h, g_wvt_l, row0, col0, DIM,
               kstart, DIM / WVO_SPLIT, sm, acc);

    float* dst = g_wvop + (size_t)blockIdx.z * DIM * DIM;
    const int lane = threadIdx.x & 31, wid = threadIdx.x >> 5;
    const int warp_m = (wid >> 2) * 64, warp_n = (wid & 3) * 32;
    #pragma unroll
    for (int mt = 0; mt < 4; mt++) {
        int r0 = row0 + warp_m + mt*16 + (lane >> 2);
        #pragma unroll
        for (int nt = 0; nt < 4; nt++) {
            int col = col0 + warp_n + nt*8 + (lane & 3) * 2;
            #pragma unroll
            for (int half = 0; half < 2; half++) {
                int r = r0 + half*8;
                float2 f2 = {acc[mt][nt][2*half], acc[mt][nt][2*half+1]};
                *(float2*)(dst + (size_t)r * DIM + col) = f2;
            }
        }
    }
}

// Reduce split-K partials, round to fp16 Wvo.
__global__ void __launch_bounds__(256) wvo_reduce_kernel()
{
    size_t i = ((size_t)blockIdx.x * 256 + threadIdx.x) * 4;
    float4 s = *(const float4*)(g_wvop + i);
    #pragma unroll
    for (int z = 1; z < WVO_SPLIT; z++) {
        float4 p = *(const float4*)(g_wvop + (size_t)z * DIM * DIM + i);
        s.x += p.x; s.y += p.y; s.z += p.z; s.w += p.w;
    }
    __half h[4];
    h[0] = __float2half_rn(s.x);
    h[1] = __float2half_rn(s.y);
    h[2] = __float2half_rn(s.z);
    h[3] = __float2half_rn(s.w);
    *(uint2*)(g_wvoh + i) = *(uint2*)h;
}

// ---------------------------------------------------------------------------
// cum_out: out = bo - 1e9 * (Ph + Pl) @ Wh^T   (fp16 x2 scheme)
// grid (8, 64), block 256, smem 61440.
// ---------------------------------------------------------------------------
__global__ void __launch_bounds__(256, 2) cum_out_kernel(
    const float* __restrict__ bo, float* __restrict__ out)
{
    extern __shared__ char smraw[];
    uint32_t sm = smem_to_u32(smraw);
    const int tid = threadIdx.x, lane = tid & 31, wid = tid >> 5;
    const int warp_m = (wid >> 2) * 64, warp_n = (wid & 3) * 32;
    const int row0 = blockIdx.y * 128, col0 = blockIdx.x * 128;
    const int lr = tid >> 2;
    const int lc = (tid & 3) * 8;
    const uint32_t so1 = (uint32_t)((lr * PGP + lc) * 2);
    const uint32_t so2 = (uint32_t)(((lr + 64) * PGP + lc) * 2);

    float acc[4][4][4] = {};

    auto issue = [&](int kt, int buf) {
        uint32_t base = sm + buf * STAGE2;
        const __half* agh = g_pxh + (size_t)(row0 + lr) * DIM + kt * 32 + lc;
        const __half* agl = g_pxl + (size_t)(row0 + lr) * DIM + kt * 32 + lc;
        const __half* bgh = g_wvoh + (size_t)(col0 + lr) * DIM + kt * 32 + lc;
        CP16(base + so1, agh);
        CP16(base + so2, agh + 64 * DIM);
        CP16(base + TILEB + so1, agl);
        CP16(base + TILEB + so2, agl + 64 * DIM);
        CP16(base + 2 * TILEB + so1, bgh);
        CP16(base + 2 * TILEB + so2, bgh + 64 * DIM);
        CP_COMMIT();
    };

    issue(0, 0);
    const int nkt = DIM / 32;
    for (int kt = 0; kt < nkt; kt++) {
        CP_WAIT0();
        __syncthreads();
        if (kt + 1 < nkt) issue(kt + 1, (kt + 1) & 1);

        const uint32_t ah_b = sm + (kt & 1) * STAGE2;
        const uint32_t al_b = ah_b + TILEB;
        const uint32_t bh_b = ah_b + 2 * TILEB;

        #pragma unroll
        for (int ks = 0; ks < 2; ks++) {
            uint32_t af[4][4], bfh[2][4];
            #pragma unroll
            for (int mt = 0; mt < 4; mt++) {
                uint32_t ad = ah_b + (uint32_t)(((warp_m + mt*16 + (lane&15))*PGP + ks*16)*2 + (lane&16));
                LDSM_X4(af[mt], ad);
            }
            #pragma unroll
            for (int p = 0; p < 2; p++) {
                uint32_t bd = bh_b + (uint32_t)(((warp_n + p*16 + (lane&7) + ((lane&16)>>1))*PGP + ks*16)*2 + ((lane&8)<<1));
                LDSM_X4(bfh[p], bd);
            }
            #pragma unroll
            for (int mt = 0; mt < 4; mt++)
                #pragma unroll
                for (int p = 0; p < 2; p++) {
                    MMA_F16(acc[mt][2*p],   af[mt], bfh[p][0], bfh[p][1]);
                    MMA_F16(acc[mt][2*p+1], af[mt], bfh[p][2], bfh[p][3]);
                }
            {   // Pl @ Wh
                uint32_t alf[4][4];
                #pragma unroll
                for (int mt = 0; mt < 4; mt++) {
                    uint32_t ad = al_b + (uint32_t)(((warp_m + mt*16 + (lane&15))*PGP + ks*16)*2 + (lane&16));
                    LDSM_X4(alf[mt], ad);
                }
                #pragma unroll
                for (int mt = 0; mt < 4; mt++)
                    #pragma unroll
                    for (int p = 0; p < 2; p++) {
                        MMA_F16(acc[mt][2*p],   alf[mt], bfh[p][0], bfh[p][1]);
                        MMA_F16(acc[mt][2*p+1], alf[mt], bfh[p][2], bfh[p][3]);
                    }
            }
        }
    }

    #pragma unroll
    for (int mt = 0; mt < 4; mt++) {
        int r0 = row0 + warp_m + mt*16 + (lane >> 2);
        #pragma unroll
        for (int nt = 0; nt < 4; nt++) {
            int col = col0 + warp_n + nt*8 + (lane & 3) * 2;
            float2 bb = *(const float2*)(bo + col);
            #pragma unroll
            for (int half = 0; half < 2; half++) {
                int r = r0 + half*8;
                float2 f2 = {bb.x - NEGC * acc[mt][nt][2*half],
                             bb.y - NEGC * acc[mt][nt][2*half+1]};
                *(float2*)(out + (size_t)r * DIM + col) = f2;
            }
        }
    }
}

// ---------------------------------------------------------------------------
extern "C" void kernel_launch(void* const* d_in, const int* in_sizes, int n_in,
                              void* d_out, int out_size)
{
    const float* x  = (const float*)d_in[0];
    const float* wv = (const float*)d_in[3];
    const float* wo = (const float*)d_in[4];
    const float* bo = (const float*)d_in[5];
    float* out = (float*)d_out;

    cudaFuncSetAttribute(wvo_kernel,
                         cudaFuncAttributeMaxDynamicSharedMemorySize, SM_X3);
    cudaFuncSetAttribute(cum_out_kernel,
                         cudaFuncAttributeMaxDynamicSharedMemorySize, SM_X2);

    split_wo_kernel<<<DIM*DIM/(256*4), 256>>>(wo);
    transpose_wv_kernel<<<dim3(32, 32), 256>>>(wv);
    prefix_x_a_kernel<<<dim3(NB, NCH, 4), 256>>>(x);
    prefix_x_b_kernel<<<dim3(NB, NCH, 4), 256>>>(x);
    wvo_kernel<<<dim3(DIM/128, DIM/128, WVO_SPLIT), 256, SM_X3>>>();
    wvo_reduce_kernel<<<DIM*DIM/(256*4), 256>>>();
    cum_out_kernel<<<dim3(DIM/128, NS/128), 256, SM_X2>>>(bo, out);
}

// round 13
// speedup vs baseline: 6.1982x; 1.3816x over previous
#include <cuda_runtime.h>
#include <cuda_bf16.h>
#include <cuda_fp16.h>
#include <cstdint>

// Problem constants
#define NB    4
#define SEQ   2048
#define DIM   1024
#define NS    (NB*SEQ)          // 8192
#define NEGC  1000000000.0f
#define NCH   32                // prefix chunks per batch
#define CHR   (SEQ/NCH)         // 64 rows per chunk

// ---------------------------------------------------------------------------
// Scratch (device globals)
// ---------------------------------------------------------------------------
#define WVO_SPLIT 8
__device__ __align__(16) float g_xsum[NB][NCH][DIM];                     // chunk sums of x
__device__ __align__(16) float g_wvop[(size_t)WVO_SPLIT * DIM * DIM];    // split-K partials
__device__ __align__(16) __half g_pxh[(size_t)NS * DIM];                 // prefix(X) fp16
__device__ __align__(16) __half g_wvoh[(size_t)DIM * DIM];               // Wvo fp16
__device__ __align__(16) __nv_bfloat16 g_woh[(size_t)DIM * DIM];         // Wo hi bf16
__device__ __align__(16) __nv_bfloat16 g_wol[(size_t)DIM * DIM];         // Wo lo bf16
__device__ __align__(16) __nv_bfloat16 g_wvt_h[(size_t)DIM * DIM];       // Wv^T hi
__device__ __align__(16) __nv_bfloat16 g_wvt_l[(size_t)DIM * DIM];       // Wv^T lo

// ---------------------------------------------------------------------------
// PTX helpers
// ---------------------------------------------------------------------------
__device__ __forceinline__ uint32_t smem_to_u32(const void* p) {
    uint32_t a;
    asm("{ .reg .u64 t; cvta.to.shared.u64 t, %1; cvt.u32.u64 %0, t; }"
        : "=r"(a) : "l"(p));
    return a;
}

#define CP16(dst, src) \
    asm volatile("cp.async.cg.shared.global [%0], [%1], 16;" \
                 :: "r"((uint32_t)(dst)), "l"(src))
#define CP_COMMIT() asm volatile("cp.async.commit_group;" ::: "memory")
#define CP_WAIT0()  asm volatile("cp.async.wait_group 0;" ::: "memory")

#define LDSM_X4(r, addr) \
    asm volatile("ldmatrix.sync.aligned.m8n8.x4.shared.b16 {%0,%1,%2,%3}, [%4];" \
        : "=r"((r)[0]), "=r"((r)[1]), "=r"((r)[2]), "=r"((r)[3]) : "r"(addr))

#define MMA_BF16(c, a, b0, b1) \
    asm volatile("mma.sync.aligned.m16n8k16.row.col.f32.bf16.bf16.f32 " \
        "{%0,%1,%2,%3}, {%4,%5,%6,%7}, {%8,%9}, {%0,%1,%2,%3};" \
        : "+f"((c)[0]), "+f"((c)[1]), "+f"((c)[2]), "+f"((c)[3]) \
        : "r"((a)[0]), "r"((a)[1]), "r"((a)[2]), "r"((a)[3]), "r"(b0), "r"(b1))

#define MMA_F16(c, a, b0, b1) \
    asm volatile("mma.sync.aligned.m16n8k16.row.col.f32.f16.f16.f32 " \
        "{%0,%1,%2,%3}, {%4,%5,%6,%7}, {%8,%9}, {%0,%1,%2,%3};" \
        : "+f"((c)[0]), "+f"((c)[1]), "+f"((c)[2]), "+f"((c)[3]) \
        : "r"((a)[0]), "r"((a)[1]), "r"((a)[2]), "r"((a)[3]), "r"(b0), "r"(b1))

// ---------------------------------------------------------------------------
// split helpers / prep kernels
// ---------------------------------------------------------------------------
__device__ __forceinline__ void split4bf(float4 v, __nv_bfloat16* h, __nv_bfloat16* l)
{
    h[0] = __float2bfloat16(v.x); l[0] = __float2bfloat16(v.x - __bfloat162float(h[0]));
    h[1] = __float2bfloat16(v.y); l[1] = __float2bfloat16(v.y - __bfloat162float(h[1]));
    h[2] = __float2bfloat16(v.z); l[2] = __float2bfloat16(v.z - __bfloat162float(h[2]));
    h[3] = __float2bfloat16(v.w); l[3] = __float2bfloat16(v.w - __bfloat162float(h[3]));
}

__global__ void __launch_bounds__(256) split_wo_kernel(const float* __restrict__ wo)
{
    size_t i = ((size_t)blockIdx.x * 256 + threadIdx.x) * 4;
    float4 v = *(const float4*)(wo + i);
    __nv_bfloat16 h[4], l[4];
    split4bf(v, h, l);
    *(uint2*)(g_woh + i) = *(uint2*)h;
    *(uint2*)(g_wol + i) = *(uint2*)l;
}

// Transpose Wv (fp32 [k][j]) -> Wv^T hi/lo bf16 [j][k]
__global__ void __launch_bounds__(256) transpose_wv_kernel(const float* __restrict__ wv)
{
    __shared__ float tile[32][33];
    const int bx = blockIdx.x * 32;
    const int by = blockIdx.y * 32;
    const int tx = threadIdx.x & 31, ty = threadIdx.x >> 5;
    #pragma unroll
    for (int i = 0; i < 4; i++)
        tile[ty + 8*i][tx] = wv[(size_t)(by + ty + 8*i) * DIM + bx + tx];
    __syncthreads();
    #pragma unroll
    for (int i = 0; i < 4; i++) {
        float v = tile[tx][ty + 8*i];
        __nv_bfloat16 h = __float2bfloat16(v);
        __nv_bfloat16 l = __float2bfloat16(v - __bfloat162float(h));
        size_t o = (size_t)(bx + ty + 8*i) * DIM + by + tx;
        g_wvt_h[o] = h;
        g_wvt_l[o] = l;
    }
}

// ---------------------------------------------------------------------------
// Prefix of X, pass A: per-(batch, 64-row chunk, d) partial sums.
// grid (NB, NCH, 4), block 256.
// ---------------------------------------------------------------------------
__global__ void __launch_bounds__(256) prefix_x_a_kernel(const float* __restrict__ x)
{
    const int n = blockIdx.x, ch = blockIdx.y;
    const int d = blockIdx.z * 256 + threadIdx.x;
    const float* p = x + ((size_t)(n * SEQ) + ch * CHR) * DIM + d;
    float s = 0.0f;
    for (int t = 0; t < CHR; t++) s += p[(size_t)t * DIM];
    g_xsum[n][ch][d] = s;
}

// Pass B: exclusive prefix of X -> fp16. grid (NB, NCH, 4).
__global__ void __launch_bounds__(256) prefix_x_b_kernel(const float* __restrict__ x)
{
    const int n = blockIdx.x, ch = blockIdx.y;
    const int d = blockIdx.z * 256 + threadIdx.x;
    float run = 0.0f;
    for (int c = 0; c < ch; c++) run += g_xsum[n][c][d];
    const float* p = x + ((size_t)(n * SEQ) + ch * CHR) * DIM + d;
    size_t o = ((size_t)(n * SEQ) + ch * CHR) * DIM + d;
    for (int t = 0; t < CHR; t++) {
        g_pxh[o] = __float2half_rn(run);
        run += p[(size_t)t * DIM];
        o += DIM;
    }
}

// ---------------------------------------------------------------------------
// Shared GEMM geometry
// ---------------------------------------------------------------------------
#define PGP   40
#define TILEB (128*PGP*2)
#define STAGE3 (4*TILEB)
#define SM_X3 (2*STAGE3)     // 81920 B  (bf16 x3: Ah Al Bh Bl)
#define STAGE1 (2*TILEB)
#define SM_X1 (2*STAGE1)     // 40960 B  (fp16 x1: Ah Bh)

// ---------------------------------------------------------------------------
// bf16 x3 GEMM (AhBh + AlBh + AhBl) over K range. Used for Wvo only.
// ---------------------------------------------------------------------------
__device__ __forceinline__ void gemm128_x3(
    const __nv_bfloat16* __restrict__ Agh, const __nv_bfloat16* __restrict__ Agl,
    const __nv_bfloat16* __restrict__ Bgh, const __nv_bfloat16* __restrict__ Bgl,
    int row0, int col0, int kdim, int kstart, int klen,
    uint32_t sm, float acc[4][4][4])
{
    const int tid = threadIdx.x, lane = tid & 31, wid = tid >> 5;
    const int warp_m = (wid >> 2) * 64, warp_n = (wid & 3) * 32;
    const int lr = tid >> 2;
    const int lc = (tid & 3) * 8;
    const uint32_t so1 = (uint32_t)((lr * PGP + lc) * 2);
    const uint32_t so2 = (uint32_t)(((lr + 64) * PGP + lc) * 2);

    auto issue = [&](int kt, int buf) {
        uint32_t base = sm + buf * STAGE3;
        const __nv_bfloat16* agh = Agh + (size_t)(row0 + lr) * kdim + kstart + kt * 32 + lc;
        const __nv_bfloat16* agl = Agl + (size_t)(row0 + lr) * kdim + kstart + kt * 32 + lc;
        const __nv_bfloat16* bgh = Bgh + (size_t)(col0 + lr) * kdim + kstart + kt * 32 + lc;
        const __nv_bfloat16* bgl = Bgl + (size_t)(col0 + lr) * kdim + kstart + kt * 32 + lc;
        CP16(base + so1, agh);
        CP16(base + so2, agh + 64 * kdim);
        CP16(base + TILEB + so1, agl);
        CP16(base + TILEB + so2, agl + 64 * kdim);
        CP16(base + 2 * TILEB + so1, bgh);
        CP16(base + 2 * TILEB + so2, bgh + 64 * kdim);
        CP16(base + 3 * TILEB + so1, bgl);
        CP16(base + 3 * TILEB + so2, bgl + 64 * kdim);
        CP_COMMIT();
    };

    issue(0, 0);
    const int nkt = klen / 32;
    for (int kt = 0; kt < nkt; kt++) {
        CP_WAIT0();
        __syncthreads();
        if (kt + 1 < nkt) issue(kt + 1, (kt + 1) & 1);

        const uint32_t ah_b = sm + (kt & 1) * STAGE3;
        const uint32_t al_b = ah_b + TILEB;
        const uint32_t bh_b = ah_b + 2 * TILEB;
        const uint32_t bl_b = ah_b + 3 * TILEB;

        #pragma unroll
        for (int ks = 0; ks < 2; ks++) {
            uint32_t af[4][4], bfh[2][4];
            #pragma unroll
            for (int mt = 0; mt < 4; mt++) {
                uint32_t ad = ah_b + (uint32_t)(((warp_m + mt*16 + (lane&15))*PGP + ks*16)*2 + (lane&16));
                LDSM_X4(af[mt], ad);
            }
            #pragma unroll
            for (int p = 0; p < 2; p++) {
                uint32_t bd = bh_b + (uint32_t)(((warp_n + p*16 + (lane&7) + ((lane&16)>>1))*PGP + ks*16)*2 + ((lane&8)<<1));
                LDSM_X4(bfh[p], bd);
            }
            #pragma unroll
            for (int mt = 0; mt < 4; mt++)
                #pragma unroll
                for (int p = 0; p < 2; p++) {
                    MMA_BF16(acc[mt][2*p],   af[mt], bfh[p][0], bfh[p][1]);
                    MMA_BF16(acc[mt][2*p+1], af[mt], bfh[p][2], bfh[p][3]);
                }
            {   // Al @ Bh
                uint32_t alf[4][4];
                #pragma unroll
                for (int mt = 0; mt < 4; mt++) {
                    uint32_t ad = al_b + (uint32_t)(((warp_m + mt*16 + (lane&15))*PGP + ks*16)*2 + (lane&16));
                    LDSM_X4(alf[mt], ad);
                }
                #pragma unroll
                for (int mt = 0; mt < 4; mt++)
                    #pragma unroll
                    for (int p = 0; p < 2; p++) {
                        MMA_BF16(acc[mt][2*p],   alf[mt], bfh[p][0], bfh[p][1]);
                        MMA_BF16(acc[mt][2*p+1], alf[mt], bfh[p][2], bfh[p][3]);
                    }
            }
            {   // Ah @ Bl
                uint32_t blf[2][4];
                #pragma unroll
                for (int p = 0; p < 2; p++) {
                    uint32_t bd = bl_b + (uint32_t)(((warp_n + p*16 + (lane&7) + ((lane&16)>>1))*PGP + ks*16)*2 + ((lane&8)<<1));
                    LDSM_X4(blf[p], bd);
                }
                #pragma unroll
                for (int mt = 0; mt < 4; mt++)
                    #pragma unroll
                    for (int p = 0; p < 2; p++) {
                        MMA_BF16(acc[mt][2*p],   af[mt], blf[p][0], blf[p][1]);
                        MMA_BF16(acc[mt][2*p+1], af[mt], blf[p][2], blf[p][3]);
                    }
            }
        }
    }
}

// ---------------------------------------------------------------------------
// Wvo split-K partials (bf16 x3): grid (8, 8, 8).
// ---------------------------------------------------------------------------
__global__ void __launch_bounds__(256, 2) wvo_kernel()
{
    extern __shared__ char smraw[];
    uint32_t sm = smem_to_u32(smraw);
    const int row0 = blockIdx.y * 128, col0 = blockIdx.x * 128;
    const int kstart = blockIdx.z * (DIM / WVO_SPLIT);

    float acc[4][4][4] = {};
    gemm128_x3(g_woh, g_wol, g_wvt_h, g_wvt_l, row0, col0, DIM,
               kstart, DIM / WVO_SPLIT, sm, acc);

    float* dst = g_wvop + (size_t)blockIdx.z * DIM * DIM;
    const int lane = threadIdx.x & 31, wid = threadIdx.x >> 5;
    const int warp_m = (wid >> 2) * 64, warp_n = (wid & 3) * 32;
    #pragma unroll
    for (int mt = 0; mt < 4; mt++) {
        int r0 = row0 + warp_m + mt*16 + (lane >> 2);
        #pragma unroll
        for (int nt = 0; nt < 4; nt++) {
            int col = col0 + warp_n + nt*8 + (lane & 3) * 2;
            #pragma unroll
            for (int half = 0; half < 2; half++) {
                int r = r0 + half*8;
                float2 f2 = {acc[mt][nt][2*half], acc[mt][nt][2*half+1]};
                *(float2*)(dst + (size_t)r * DIM + col) = f2;
            }
        }
    }
}

// Reduce split-K partials, round to fp16 Wvo.
__global__ void __launch_bounds__(256) wvo_reduce_kernel()
{
    size_t i = ((size_t)blockIdx.x * 256 + threadIdx.x) * 4;
    float4 s = *(const float4*)(g_wvop + i);
    #pragma unroll
    for (int z = 1; z < WVO_SPLIT; z++) {
        float4 p = *(const float4*)(g_wvop + (size_t)z * DIM * DIM + i);
        s.x += p.x; s.y += p.y; s.z += p.z; s.w += p.w;
    }
    __half h[4];
    h[0] = __float2half_rn(s.x);
    h[1] = __float2half_rn(s.y);
    h[2] = __float2half_rn(s.z);
    h[3] = __float2half_rn(s.w);
    *(uint2*)(g_wvoh + i) = *(uint2*)h;
}

// ---------------------------------------------------------------------------
// cum_out: out = bo - 1e9 * Ph @ Wh^T   (fp16 x1)
// grid (8, 64), block 256, smem 40960.
// ---------------------------------------------------------------------------
__global__ void __launch_bounds__(256, 2) cum_out_kernel(
    const float* __restrict__ bo, float* __restrict__ out)
{
    extern __shared__ char smraw[];
    uint32_t sm = smem_to_u32(smraw);
    const int tid = threadIdx.x, lane = tid & 31, wid = tid >> 5;
    const int warp_m = (wid >> 2) * 64, warp_n = (wid & 3) * 32;
    const int row0 = blockIdx.y * 128, col0 = blockIdx.x * 128;
    const int lr = tid >> 2;
    const int lc = (tid & 3) * 8;
    const uint32_t so1 = (uint32_t)((lr * PGP + lc) * 2);
    const uint32_t so2 = (uint32_t)(((lr + 64) * PGP + lc) * 2);

    float acc[4][4][4] = {};

    auto issue = [&](int kt, int buf) {
        uint32_t base = sm + buf * STAGE1;
        const __half* agh = g_pxh + (size_t)(row0 + lr) * DIM + kt * 32 + lc;
        const __half* bgh = g_wvoh + (size_t)(col0 + lr) * DIM + kt * 32 + lc;
        CP16(base + so1, agh);
        CP16(base + so2, agh + 64 * DIM);
        CP16(base + TILEB + so1, bgh);
        CP16(base + TILEB + so2, bgh + 64 * DIM);
        CP_COMMIT();
    };

    issue(0, 0);
    const int nkt = DIM / 32;
    for (int kt = 0; kt < nkt; kt++) {
        CP_WAIT0();
        __syncthreads();
        if (kt + 1 < nkt) issue(kt + 1, (kt + 1) & 1);

        const uint32_t ah_b = sm + (kt & 1) * STAGE1;
        const uint32_t bh_b = ah_b + TILEB;

        #pragma unroll
        for (int ks = 0; ks < 2; ks++) {
            uint32_t af[4][4], bfh[2][4];
            #pragma unroll
            for (int mt = 0; mt < 4; mt++) {
                uint32_t ad = ah_b + (uint32_t)(((warp_m + mt*16 + (lane&15))*PGP + ks*16)*2 + (lane&16));
                LDSM_X4(af[mt], ad);
            }
            #pragma unroll
            for (int p = 0; p < 2; p++) {
                uint32_t bd = bh_b + (uint32_t)(((warp_n + p*16 + (lane&7) + ((lane&16)>>1))*PGP + ks*16)*2 + ((lane&8)<<1));
                LDSM_X4(bfh[p], bd);
            }
            #pragma unroll
            for (int mt = 0; mt < 4; mt++)
                #pragma unroll
                for (int p = 0; p < 2; p++) {
                    MMA_F16(acc[mt][2*p],   af[mt], bfh[p][0], bfh[p][1]);
                    MMA_F16(acc[mt][2*p+1], af[mt], bfh[p][2], bfh[p][3]);
                }
        }
    }

    #pragma unroll
    for (int mt = 0; mt < 4; mt++) {
        int r0 = row0 + warp_m + mt*16 + (lane >> 2);
        #pragma unroll
        for (int nt = 0; nt < 4; nt++) {
            int col = col0 + warp_n + nt*8 + (lane & 3) * 2;
            float2 bb = *(const float2*)(bo + col);
            #pragma unroll
            for (int half = 0; half < 2; half++) {
                int r = r0 + half*8;
                float2 f2 = {bb.x - NEGC * acc[mt][nt][2*half],
                             bb.y - NEGC * acc[mt][nt][2*half+1]};
                *(float2*)(out + (size_t)r * DIM + col) = f2;
            }
        }
    }
}

// ---------------------------------------------------------------------------
extern "C" void kernel_launch(void* const* d_in, const int* in_sizes, int n_in,
                              void* d_out, int out_size)
{
    const float* x  = (const float*)d_in[0];
    const float* wv = (const float*)d_in[3];
    const float* wo = (const float*)d_in[4];
    const float* bo = (const float*)d_in[5];
    float* out = (float*)d_out;

    cudaFuncSetAttribute(wvo_kernel,
                         cudaFuncAttributeMaxDynamicSharedMemorySize, SM_X3);
    cudaFuncSetAttribute(cum_out_kernel,
                         cudaFuncAttributeMaxDynamicSharedMemorySize, SM_X1);

    split_wo_kernel<<<DIM*DIM/(256*4), 256>>>(wo);
    transpose_wv_kernel<<<dim3(32, 32), 256>>>(wv);
    prefix_x_a_kernel<<<dim3(NB, NCH, 4), 256>>>(x);
    prefix_x_b_kernel<<<dim3(NB, NCH, 4), 256>>>(x);
    wvo_kernel<<<dim3(DIM/128, DIM/128, WVO_SPLIT), 256, SM_X3>>>();
    wvo_reduce_kernel<<<DIM*DIM/(256*4), 256>>>();
    cum_out_kernel<<<dim3(DIM/128, NS/128), 256, SM_X1>>>(bo, out);
}

// round 14
// speedup vs baseline: 6.4440x; 1.0397x over previous
#include <cuda_runtime.h>
#include <cuda_fp16.h>
#include <cstdint>

// Problem constants
#define NB    4
#define SEQ   2048
#define DIM   1024
#define NS    (NB*SEQ)          // 8192
#define NEGC  1000000000.0f
#define NCH   64                // prefix chunks per batch
#define CHR   (SEQ/NCH)         // 32 rows per chunk

// ---------------------------------------------------------------------------
// Scratch (device globals)
// ---------------------------------------------------------------------------
#define WVO_SPLIT 8
__device__ __align__(16) float g_xsum[NB][NCH][DIM];                     // chunk sums of x
__device__ __align__(16) float g_wvop[(size_t)WVO_SPLIT * DIM * DIM];    // split-K partials
__device__ __align__(16) __half g_pxh[(size_t)NS * DIM];                 // prefix(X) fp16
__device__ __align__(16) __half g_wvoh[(size_t)DIM * DIM];               // Wvo fp16
__device__ __align__(16) __half g_woh[(size_t)DIM * DIM];                // Wo hi fp16
__device__ __align__(16) __half g_wol[(size_t)DIM * DIM];                // Wo lo fp16
__device__ __align__(16) __half g_wvt[(size_t)DIM * DIM];                // Wv^T fp16

// ---------------------------------------------------------------------------
// PTX helpers
// ---------------------------------------------------------------------------
__device__ __forceinline__ uint32_t smem_to_u32(const void* p) {
    uint32_t a;
    asm("{ .reg .u64 t; cvta.to.shared.u64 t, %1; cvt.u32.u64 %0, t; }"
        : "=r"(a) : "l"(p));
    return a;
}

#define CP16(dst, src) \
    asm volatile("cp.async.cg.shared.global [%0], [%1], 16;" \
                 :: "r"((uint32_t)(dst)), "l"(src))
#define CP_COMMIT() asm volatile("cp.async.commit_group;" ::: "memory")
#define CP_WAIT0()  asm volatile("cp.async.wait_group 0;" ::: "memory")

#define LDSM_X4(r, addr) \
    asm volatile("ldmatrix.sync.aligned.m8n8.x4.shared.b16 {%0,%1,%2,%3}, [%4];" \
        : "=r"((r)[0]), "=r"((r)[1]), "=r"((r)[2]), "=r"((r)[3]) : "r"(addr))

#define MMA_F16(c, a, b0, b1) \
    asm volatile("mma.sync.aligned.m16n8k16.row.col.f32.f16.f16.f32 " \
        "{%0,%1,%2,%3}, {%4,%5,%6,%7}, {%8,%9}, {%0,%1,%2,%3};" \
        : "+f"((c)[0]), "+f"((c)[1]), "+f"((c)[2]), "+f"((c)[3]) \
        : "r"((a)[0]), "r"((a)[1]), "r"((a)[2]), "r"((a)[3]), "r"(b0), "r"(b1))

// ---------------------------------------------------------------------------
// prep kernels
// ---------------------------------------------------------------------------
__global__ void __launch_bounds__(256) split_wo_kernel(const float* __restrict__ wo)
{
    size_t i = ((size_t)blockIdx.x * 256 + threadIdx.x) * 4;
    float4 v = *(const float4*)(wo + i);
    __half h[4], l[4];
    h[0] = __float2half_rn(v.x); l[0] = __float2half_rn(v.x - __half2float(h[0]));
    h[1] = __float2half_rn(v.y); l[1] = __float2half_rn(v.y - __half2float(h[1]));
    h[2] = __float2half_rn(v.z); l[2] = __float2half_rn(v.z - __half2float(h[2]));
    h[3] = __float2half_rn(v.w); l[3] = __float2half_rn(v.w - __half2float(h[3]));
    *(uint2*)(g_woh + i) = *(uint2*)h;
    *(uint2*)(g_wol + i) = *(uint2*)l;
}

// Transpose Wv (fp32 [k][j]) -> Wv^T fp16 [j][k]
__global__ void __launch_bounds__(256) transpose_wv_kernel(const float* __restrict__ wv)
{
    __shared__ float tile[32][33];
    const int bx = blockIdx.x * 32;
    const int by = blockIdx.y * 32;
    const int tx = threadIdx.x & 31, ty = threadIdx.x >> 5;
    #pragma unroll
    for (int i = 0; i < 4; i++)
        tile[ty + 8*i][tx] = wv[(size_t)(by + ty + 8*i) * DIM + bx + tx];
    __syncthreads();
    #pragma unroll
    for (int i = 0; i < 4; i++) {
        float v = tile[tx][ty + 8*i];
        g_wvt[(size_t)(bx + ty + 8*i) * DIM + by + tx] = __float2half_rn(v);
    }
}

// ---------------------------------------------------------------------------
// Prefix of X, pass A (vectorized): per-(batch, 32-row chunk) column sums.
// grid (NB, NCH), block 256, 4 columns/thread.
// ---------------------------------------------------------------------------
__global__ void __launch_bounds__(256) prefix_x_a_kernel(const float* __restrict__ x)
{
    const int n = blockIdx.x, ch = blockIdx.y;
    const int d = threadIdx.x * 4;
    const float* p = x + ((size_t)(n * SEQ) + ch * CHR) * DIM + d;
    float4 s = {0.f, 0.f, 0.f, 0.f};
    #pragma unroll 4
    for (int t = 0; t < CHR; t++) {
        float4 v = *(const float4*)(p + (size_t)t * DIM);
        s.x += v.x; s.y += v.y; s.z += v.z; s.w += v.w;
    }
    *(float4*)(&g_xsum[n][ch][d]) = s;
}

// Pass B (vectorized): exclusive prefix of X -> fp16. grid (NB, NCH), block 256.
__global__ void __launch_bounds__(256) prefix_x_b_kernel(const float* __restrict__ x)
{
    const int n = blockIdx.x, ch = blockIdx.y;
    const int d = threadIdx.x * 4;
    float4 run = {0.f, 0.f, 0.f, 0.f};
    for (int c = 0; c < ch; c++) {
        float4 v = *(const float4*)(&g_xsum[n][c][d]);
        run.x += v.x; run.y += v.y; run.z += v.z; run.w += v.w;
    }
    const float* p = x + ((size_t)(n * SEQ) + ch * CHR) * DIM + d;
    size_t o = ((size_t)(n * SEQ) + ch * CHR) * DIM + d;
    #pragma unroll 2
    for (int t = 0; t < CHR; t++) {
        __half h[4];
        h[0] = __float2half_rn(run.x);
        h[1] = __float2half_rn(run.y);
        h[2] = __float2half_rn(run.z);
        h[3] = __float2half_rn(run.w);
        *(uint2*)(g_pxh + o) = *(uint2*)h;
        float4 v = *(const float4*)(p + (size_t)t * DIM);
        run.x += v.x; run.y += v.y; run.z += v.z; run.w += v.w;
        o += DIM;
    }
}

// ---------------------------------------------------------------------------
// fp16 GEMM core: C(128x128) = A@B^T over K range [kstart, kstart+klen).
// 8 warps (2m x 4n), warp tile 64x32, BK=32, 2-stage cp.async,
// one __syncthreads per BK tile. X2 adds Al@Bh.
// ---------------------------------------------------------------------------
#define PGP   40
#define TILEB (128*PGP*2)
#define SM_X2 (2*3*TILEB)    // 61440 B  (Ah Al Bh)
#define SM_X1 (2*2*TILEB)    // 40960 B  (Ah Bh)

template<bool X2>
__device__ __forceinline__ void gemm128_f16(
    const __half* __restrict__ Agh, const __half* __restrict__ Agl,
    const __half* __restrict__ Bgh,
    int row0, int col0, int kdim, int kstart, int klen,
    uint32_t sm, float acc[4][4][4])
{
    const int tid = threadIdx.x, lane = tid & 31, wid = tid >> 5;
    const int warp_m = (wid >> 2) * 64, warp_n = (wid & 3) * 32;
    const int STAGE = (X2 ? 3 : 2) * TILEB;
    const int lr = tid >> 2;
    const int lc = (tid & 3) * 8;
    const uint32_t so1 = (uint32_t)((lr * PGP + lc) * 2);
    const uint32_t so2 = (uint32_t)(((lr + 64) * PGP + lc) * 2);

    auto issue = [&](int kt, int buf) {
        uint32_t base = sm + buf * STAGE;
        const __half* agh = Agh + (size_t)(row0 + lr) * kdim + kstart + kt * 32 + lc;
        const __half* bgh = Bgh + (size_t)(col0 + lr) * kdim + kstart + kt * 32 + lc;
        CP16(base + so1, agh);
        CP16(base + so2, agh + 64 * kdim);
        uint32_t bb = base + (X2 ? 2 : 1) * TILEB;
        CP16(bb + so1, bgh);
        CP16(bb + so2, bgh + 64 * kdim);
        if (X2) {
            const __half* agl = Agl + (size_t)(row0 + lr) * kdim + kstart + kt * 32 + lc;
            CP16(base + TILEB + so1, agl);
            CP16(base + TILEB + so2, agl + 64 * kdim);
        }
        CP_COMMIT();
    };

    issue(0, 0);
    const int nkt = klen / 32;
    for (int kt = 0; kt < nkt; kt++) {
        CP_WAIT0();
        __syncthreads();
        if (kt + 1 < nkt) issue(kt + 1, (kt + 1) & 1);

        const uint32_t ah_b = sm + (kt & 1) * STAGE;
        const uint32_t al_b = ah_b + TILEB;
        const uint32_t bh_b = ah_b + (X2 ? 2 : 1) * TILEB;

        #pragma unroll
        for (int ks = 0; ks < 2; ks++) {
            uint32_t af[4][4], bfh[2][4];
            #pragma unroll
            for (int mt = 0; mt < 4; mt++) {
                uint32_t ad = ah_b + (uint32_t)(((warp_m + mt*16 + (lane&15))*PGP + ks*16)*2 + (lane&16));
                LDSM_X4(af[mt], ad);
            }
            #pragma unroll
            for (int p = 0; p < 2; p++) {
                uint32_t bd = bh_b + (uint32_t)(((warp_n + p*16 + (lane&7) + ((lane&16)>>1))*PGP + ks*16)*2 + ((lane&8)<<1));
                LDSM_X4(bfh[p], bd);
            }
            #pragma unroll
            for (int mt = 0; mt < 4; mt++)
                #pragma unroll
                for (int p = 0; p < 2; p++) {
                    MMA_F16(acc[mt][2*p],   af[mt], bfh[p][0], bfh[p][1]);
                    MMA_F16(acc[mt][2*p+1], af[mt], bfh[p][2], bfh[p][3]);
                }
            if (X2) {
                uint32_t alf[4][4];
                #pragma unroll
                for (int mt = 0; mt < 4; mt++) {
                    uint32_t ad = al_b + (uint32_t)(((warp_m + mt*16 + (lane&15))*PGP + ks*16)*2 + (lane&16));
                    LDSM_X4(alf[mt], ad);
                }
                #pragma unroll
                for (int mt = 0; mt < 4; mt++)
                    #pragma unroll
                    for (int p = 0; p < 2; p++) {
                        MMA_F16(acc[mt][2*p],   alf[mt], bfh[p][0], bfh[p][1]);
                        MMA_F16(acc[mt][2*p+1], alf[mt], bfh[p][2], bfh[p][3]);
                    }
            }
        }
    }
}

// ---------------------------------------------------------------------------
// Wvo split-K partials (fp16 x2): grid (8, 8, 8).
// ---------------------------------------------------------------------------
__global__ void __launch_bounds__(256, 2) wvo_kernel()
{
    extern __shared__ char smraw[];
    uint32_t sm = smem_to_u32(smraw);
    const int row0 = blockIdx.y * 128, col0 = blockIdx.x * 128;
    const int kstart = blockIdx.z * (DIM / WVO_SPLIT);

    float acc[4][4][4] = {};
    gemm128_f16<true>(g_woh, g_wol, g_wvt, row0, col0, DIM,
                      kstart, DIM / WVO_SPLIT, sm, acc);

    float* dst = g_wvop + (size_t)blockIdx.z * DIM * DIM;
    const int lane = threadIdx.x & 31, wid = threadIdx.x >> 5;
    const int warp_m = (wid >> 2) * 64, warp_n = (wid & 3) * 32;
    #pragma unroll
    for (int mt = 0; mt < 4; mt++) {
        int r0 = row0 + warp_m + mt*16 + (lane >> 2);
        #pragma unroll
        for (int nt = 0; nt < 4; nt++) {
            int col = col0 + warp_n + nt*8 + (lane & 3) * 2;
            #pragma unroll
            for (int half = 0; half < 2; half++) {
                int r = r0 + half*8;
                float2 f2 = {acc[mt][nt][2*half], acc[mt][nt][2*half+1]};
                *(float2*)(dst + (size_t)r * DIM + col) = f2;
            }
        }
    }
}

// Reduce split-K partials, round to fp16 Wvo.
__global__ void __launch_bounds__(256) wvo_reduce_kernel()
{
    size_t i = ((size_t)blockIdx.x * 256 + threadIdx.x) * 4;
    float4 s = *(const float4*)(g_wvop + i);
    #pragma unroll
    for (int z = 1; z < WVO_SPLIT; z++) {
        float4 p = *(const float4*)(g_wvop + (size_t)z * DIM * DIM + i);
        s.x += p.x; s.y += p.y; s.z += p.z; s.w += p.w;
    }
    __half h[4];
    h[0] = __float2half_rn(s.x);
    h[1] = __float2half_rn(s.y);
    h[2] = __float2half_rn(s.z);
    h[3] = __float2half_rn(s.w);
    *(uint2*)(g_wvoh + i) = *(uint2*)h;
}

// ---------------------------------------------------------------------------
// cum_out: out = bo - 1e9 * Ph @ Wvo^T   (fp16 x1). grid (8, 64).
// ---------------------------------------------------------------------------
__global__ void __launch_bounds__(256, 2) cum_out_kernel(
    const float* __restrict__ bo, float* __restrict__ out)
{
    extern __shared__ char smraw[];
    uint32_t sm = smem_to_u32(smraw);
    const int lane = threadIdx.x & 31, wid = threadIdx.x >> 5;
    const int warp_m = (wid >> 2) * 64, warp_n = (wid & 3) * 32;
    const int row0 = blockIdx.y * 128, col0 = blockIdx.x * 128;

    float acc[4][4][4] = {};
    gemm128_f16<false>(g_pxh, nullptr, g_wvoh, row0, col0, DIM, 0, DIM, sm, acc);

    #pragma unroll
    for (int mt = 0; mt < 4; mt++) {
        int r0 = row0 + warp_m + mt*16 + (lane >> 2);
        #pragma unroll
        for (int nt = 0; nt < 4; nt++) {
            int col = col0 + warp_n + nt*8 + (lane & 3) * 2;
            float2 bb = *(const float2*)(bo + col);
            #pragma unroll
            for (int half = 0; half < 2; half++) {
                int r = r0 + half*8;
                float2 f2 = {bb.x - NEGC * acc[mt][nt][2*half],
                             bb.y - NEGC * acc[mt][nt][2*half+1]};
                *(float2*)(out + (size_t)r * DIM + col) = f2;
            }
        }
    }
}

// ---------------------------------------------------------------------------
extern "C" void kernel_launch(void* const* d_in, const int* in_sizes, int n_in,
                              void* d_out, int out_size)
{
    const float* x  = (const float*)d_in[0];
    const float* wv = (const float*)d_in[3];
    const float* wo = (const float*)d_in[4];
    const float* bo = (const float*)d_in[5];
    float* out = (float*)d_out;

    cudaFuncSetAttribute(wvo_kernel,
                         cudaFuncAttributeMaxDynamicSharedMemorySize, SM_X2);
    cudaFuncSetAttribute(cum_out_kernel,
                         cudaFuncAttributeMaxDynamicSharedMemorySize, SM_X1);

    split_wo_kernel<<<DIM*DIM/(256*4), 256>>>(wo);
    transpose_wv_kernel<<<dim3(32, 32), 256>>>(wv);
    prefix_x_a_kernel<<<dim3(NB, NCH), 256>>>(x);
    prefix_x_b_kernel<<<dim3(NB, NCH), 256>>>(x);
    wvo_kernel<<<dim3(DIM/128, DIM/128, WVO_SPLIT), 256, SM_X2>>>();
    wvo_reduce_kernel<<<DIM*DIM/(256*4), 256>>>();
    cum_out_kernel<<<dim3(DIM/128, NS/128), 256, SM_X1>>>(bo, out);
}

// round 15
// speedup vs baseline: 7.1896x; 1.1157x over previous
#include <cuda_runtime.h>
#include <cuda_fp16.h>
#include <cstdint>

// Problem constants
#define NB    4
#define SEQ   2048
#define DIM   1024
#define NS    (NB*SEQ)          // 8192
#define NEGC  1000000000.0f
#define NCH   128               // prefix chunks per batch
#define CHR   (SEQ/NCH)         // 16 rows per chunk

// ---------------------------------------------------------------------------
// Scratch (device globals)
// ---------------------------------------------------------------------------
#define WVO_SPLIT 4
__device__ __align__(16) float g_xsum[NB][NCH][DIM];                     // chunk sums of x
__device__ __align__(16) float g_wvop[(size_t)WVO_SPLIT * DIM * DIM];    // split-K partials
__device__ __align__(16) __half g_pxh[(size_t)NS * DIM];                 // prefix(X) fp16
__device__ __align__(16) __half g_wvoh[(size_t)DIM * DIM];               // Wvo fp16
__device__ __align__(16) __half g_woh[(size_t)DIM * DIM];                // Wo hi fp16
__device__ __align__(16) __half g_wol[(size_t)DIM * DIM];                // Wo lo fp16
__device__ __align__(16) __half g_wvt[(size_t)DIM * DIM];                // Wv^T fp16

// ---------------------------------------------------------------------------
// PTX helpers
// ---------------------------------------------------------------------------
__device__ __forceinline__ uint32_t smem_to_u32(const void* p) {
    uint32_t a;
    asm("{ .reg .u64 t; cvta.to.shared.u64 t, %1; cvt.u32.u64 %0, t; }"
        : "=r"(a) : "l"(p));
    return a;
}

#define CP16(dst, src) \
    asm volatile("cp.async.cg.shared.global [%0], [%1], 16;" \
                 :: "r"((uint32_t)(dst)), "l"(src))
#define CP_COMMIT() asm volatile("cp.async.commit_group;" ::: "memory")
#define CP_WAIT0()  asm volatile("cp.async.wait_group 0;" ::: "memory")
#define CP_WAIT1()  asm volatile("cp.async.wait_group 1;" ::: "memory")

#define LDSM_X4(r, addr) \
    asm volatile("ldmatrix.sync.aligned.m8n8.x4.shared.b16 {%0,%1,%2,%3}, [%4];" \
        : "=r"((r)[0]), "=r"((r)[1]), "=r"((r)[2]), "=r"((r)[3]) : "r"(addr))

#define MMA_F16(c, a, b0, b1) \
    asm volatile("mma.sync.aligned.m16n8k16.row.col.f32.f16.f16.f32 " \
        "{%0,%1,%2,%3}, {%4,%5,%6,%7}, {%8,%9}, {%0,%1,%2,%3};" \
        : "+f"((c)[0]), "+f"((c)[1]), "+f"((c)[2]), "+f"((c)[3]) \
        : "r"((a)[0]), "r"((a)[1]), "r"((a)[2]), "r"((a)[3]), "r"(b0), "r"(b1))

// ---------------------------------------------------------------------------
// prep kernels
// ---------------------------------------------------------------------------
__global__ void __launch_bounds__(256) split_wo_kernel(const float* __restrict__ wo)
{
    size_t i = ((size_t)blockIdx.x * 256 + threadIdx.x) * 4;
    float4 v = *(const float4*)(wo + i);
    __half h[4], l[4];
    h[0] = __float2half_rn(v.x); l[0] = __float2half_rn(v.x - __half2float(h[0]));
    h[1] = __float2half_rn(v.y); l[1] = __float2half_rn(v.y - __half2float(h[1]));
    h[2] = __float2half_rn(v.z); l[2] = __float2half_rn(v.z - __half2float(h[2]));
    h[3] = __float2half_rn(v.w); l[3] = __float2half_rn(v.w - __half2float(h[3]));
    *(uint2*)(g_woh + i) = *(uint2*)h;
    *(uint2*)(g_wol + i) = *(uint2*)l;
}

// Transpose Wv (fp32 [k][j]) -> Wv^T fp16 [j][k]
__global__ void __launch_bounds__(256) transpose_wv_kernel(const float* __restrict__ wv)
{
    __shared__ float tile[32][33];
    const int bx = blockIdx.x * 32;
    const int by = blockIdx.y * 32;
    const int tx = threadIdx.x & 31, ty = threadIdx.x >> 5;
    #pragma unroll
    for (int i = 0; i < 4; i++)
        tile[ty + 8*i][tx] = wv[(size_t)(by + ty + 8*i) * DIM + bx + tx];
    __syncthreads();
    #pragma unroll
    for (int i = 0; i < 4; i++) {
        float v = tile[tx][ty + 8*i];
        g_wvt[(size_t)(bx + ty + 8*i) * DIM + by + tx] = __float2half_rn(v);
    }
}

// ---------------------------------------------------------------------------
// Prefix of X, pass A: per-(batch, 16-row chunk) column sums.
// grid (NB, NCH), block 256, 4 columns/thread, float4.
// ---------------------------------------------------------------------------
__global__ void __launch_bounds__(256) prefix_x_a_kernel(const float* __restrict__ x)
{
    const int n = blockIdx.x, ch = blockIdx.y;
    const int d = threadIdx.x * 4;
    const float* p = x + ((size_t)(n * SEQ) + ch * CHR) * DIM + d;
    float4 s = {0.f, 0.f, 0.f, 0.f};
    #pragma unroll
    for (int t = 0; t < CHR; t++) {
        float4 v = *(const float4*)(p + (size_t)t * DIM);
        s.x += v.x; s.y += v.y; s.z += v.z; s.w += v.w;
    }
    *(float4*)(&g_xsum[n][ch][d]) = s;
}

// Pass B: exclusive prefix of X -> fp16. grid (NB, NCH), block 256.
__global__ void __launch_bounds__(256) prefix_x_b_kernel(const float* __restrict__ x)
{
    const int n = blockIdx.x, ch = blockIdx.y;
    const int d = threadIdx.x * 4;
    float4 run = {0.f, 0.f, 0.f, 0.f};
    for (int c = 0; c < ch; c++) {
        float4 v = *(const float4*)(&g_xsum[n][c][d]);
        run.x += v.x; run.y += v.y; run.z += v.z; run.w += v.w;
    }
    const float* p = x + ((size_t)(n * SEQ) + ch * CHR) * DIM + d;
    size_t o = ((size_t)(n * SEQ) + ch * CHR) * DIM + d;
    #pragma unroll
    for (int t = 0; t < CHR; t++) {
        __half h[4];
        h[0] = __float2half_rn(run.x);
        h[1] = __float2half_rn(run.y);
        h[2] = __float2half_rn(run.z);
        h[3] = __float2half_rn(run.w);
        *(uint2*)(g_pxh + o) = *(uint2*)h;
        float4 v = *(const float4*)(p + (size_t)t * DIM);
        run.x += v.x; run.y += v.y; run.z += v.z; run.w += v.w;
        o += DIM;
    }
}

// ---------------------------------------------------------------------------
// fp16 GEMM core: C(128x128) = A@B^T over [kstart, kstart+klen).
// 8 warps (2m x 4n), warp tile 64x32, BK=32, STAGES-deep cp.async,
// one __syncthreads per BK tile. X2 adds Al@Bh.
// ---------------------------------------------------------------------------
#define PGP   40
#define TILEB (128*PGP*2)
#define SM_X2 (2*3*TILEB)    // 61440 B  (2 stages x (Ah Al Bh))
#define SM_X1 (3*2*TILEB)    // 61440 B  (3 stages x (Ah Bh))

template<bool X2, int STAGES>
__device__ __forceinline__ void gemm128_f16(
    const __half* __restrict__ Agh, const __half* __restrict__ Agl,
    const __half* __restrict__ Bgh,
    int row0, int col0, int kdim, int kstart, int klen,
    uint32_t sm, float acc[4][4][4])
{
    const int tid = threadIdx.x, lane = tid & 31, wid = tid >> 5;
    const int warp_m = (wid >> 2) * 64, warp_n = (wid & 3) * 32;
    const int STAGE = (X2 ? 3 : 2) * TILEB;
    const int lr = tid >> 2;
    const int lc = (tid & 3) * 8;
    const uint32_t so1 = (uint32_t)((lr * PGP + lc) * 2);
    const uint32_t so2 = (uint32_t)(((lr + 64) * PGP + lc) * 2);

    auto issue = [&](int kt, int buf) {
        uint32_t base = sm + buf * STAGE;
        const __half* agh = Agh + (size_t)(row0 + lr) * kdim + kstart + kt * 32 + lc;
        const __half* bgh = Bgh + (size_t)(col0 + lr) * kdim + kstart + kt * 32 + lc;
        CP16(base + so1, agh);
        CP16(base + so2, agh + 64 * kdim);
        uint32_t bb = base + (X2 ? 2 : 1) * TILEB;
        CP16(bb + so1, bgh);
        CP16(bb + so2, bgh + 64 * kdim);
        if (X2) {
            const __half* agl = Agl + (size_t)(row0 + lr) * kdim + kstart + kt * 32 + lc;
            CP16(base + TILEB + so1, agl);
            CP16(base + TILEB + so2, agl + 64 * kdim);
        }
        CP_COMMIT();
    };

    const int nkt = klen / 32;
    issue(0, 0);
    if (STAGES == 3 && nkt > 1) issue(1, 1);

    for (int kt = 0; kt < nkt; kt++) {
        if (STAGES == 3) {
            if (kt == nkt - 1) { CP_WAIT0(); } else { CP_WAIT1(); }
        } else {
            CP_WAIT0();
        }
        __syncthreads();
        if (STAGES == 3) {
            if (kt + 2 < nkt) issue(kt + 2, (kt + 2) % 3);
        } else {
            if (kt + 1 < nkt) issue(kt + 1, (kt + 1) & 1);
        }

        const uint32_t ah_b = sm + (STAGES == 3 ? (kt % 3) : (kt & 1)) * STAGE;
        const uint32_t al_b = ah_b + TILEB;
        const uint32_t bh_b = ah_b + (X2 ? 2 : 1) * TILEB;

        #pragma unroll
        for (int ks = 0; ks < 2; ks++) {
            uint32_t af[4][4], bfh[2][4];
            #pragma unroll
            for (int mt = 0; mt < 4; mt++) {
                uint32_t ad = ah_b + (uint32_t)(((warp_m + mt*16 + (lane&15))*PGP + ks*16)*2 + (lane&16));
                LDSM_X4(af[mt], ad);
            }
            #pragma unroll
            for (int p = 0; p < 2; p++) {
                uint32_t bd = bh_b + (uint32_t)(((warp_n + p*16 + (lane&7) + ((lane&16)>>1))*PGP + ks*16)*2 + ((lane&8)<<1));
                LDSM_X4(bfh[p], bd);
            }
            #pragma unroll
            for (int mt = 0; mt < 4; mt++)
                #pragma unroll
                for (int p = 0; p < 2; p++) {
                    MMA_F16(acc[mt][2*p],   af[mt], bfh[p][0], bfh[p][1]);
                    MMA_F16(acc[mt][2*p+1], af[mt], bfh[p][2], bfh[p][3]);
                }
            if (X2) {
                uint32_t alf[4][4];
                #pragma unroll
                for (int mt = 0; mt < 4; mt++) {
                    uint32_t ad = al_b + (uint32_t)(((warp_m + mt*16 + (lane&15))*PGP + ks*16)*2 + (lane&16));
                    LDSM_X4(alf[mt], ad);
                }
                #pragma unroll
                for (int mt = 0; mt < 4; mt++)
                    #pragma unroll
                    for (int p = 0; p < 2; p++) {
                        MMA_F16(acc[mt][2*p],   alf[mt], bfh[p][0], bfh[p][1]);
                        MMA_F16(acc[mt][2*p+1], alf[mt], bfh[p][2], bfh[p][3]);
                    }
            }
        }
    }
}

// ---------------------------------------------------------------------------
// Wvo split-K partials (fp16 x2): grid (8, 8, WVO_SPLIT).
// ---------------------------------------------------------------------------
__global__ void __launch_bounds__(256, 2) wvo_kernel()
{
    extern __shared__ char smraw[];
    uint32_t sm = smem_to_u32(smraw);
    const int row0 = blockIdx.y * 128, col0 = blockIdx.x * 128;
    const int kstart = blockIdx.z * (DIM / WVO_SPLIT);

    float acc[4][4][4] = {};
    gemm128_f16<true, 2>(g_woh, g_wol, g_wvt, row0, col0, DIM,
                         kstart, DIM / WVO_SPLIT, sm, acc);

    float* dst = g_wvop + (size_t)blockIdx.z * DIM * DIM;
    const int lane = threadIdx.x & 31, wid = threadIdx.x >> 5;
    const int warp_m = (wid >> 2) * 64, warp_n = (wid & 3) * 32;
    #pragma unroll
    for (int mt = 0; mt < 4; mt++) {
        int r0 = row0 + warp_m + mt*16 + (lane >> 2);
        #pragma unroll
        for (int nt = 0; nt < 4; nt++) {
            int col = col0 + warp_n + nt*8 + (lane & 3) * 2;
            #pragma unroll
            for (int half = 0; half < 2; half++) {
                int r = r0 + half*8;
                float2 f2 = {acc[mt][nt][2*half], acc[mt][nt][2*half+1]};
                *(float2*)(dst + (size_t)r * DIM + col) = f2;
            }
        }
    }
}

// Reduce split-K partials, round to fp16 Wvo.
__global__ void __launch_bounds__(256) wvo_reduce_kernel()
{
    size_t i = ((size_t)blockIdx.x * 256 + threadIdx.x) * 4;
    float4 s = *(const float4*)(g_wvop + i);
    #pragma unroll
    for (int z = 1; z < WVO_SPLIT; z++) {
        float4 p = *(const float4*)(g_wvop + (size_t)z * DIM * DIM + i);
        s.x += p.x; s.y += p.y; s.z += p.z; s.w += p.w;
    }
    __half h[4];
    h[0] = __float2half_rn(s.x);
    h[1] = __float2half_rn(s.y);
    h[2] = __float2half_rn(s.z);
    h[3] = __float2half_rn(s.w);
    *(uint2*)(g_wvoh + i) = *(uint2*)h;
}

// ---------------------------------------------------------------------------
// cum_out: out = bo - 1e9 * Ph @ Wvo^T   (fp16 x1, 3-stage). grid (8, 64).
// ---------------------------------------------------------------------------
__global__ void __launch_bounds__(256, 2) cum_out_kernel(
    const float* __restrict__ bo, float* __restrict__ out)
{
    extern __shared__ char smraw[];
    uint32_t sm = smem_to_u32(smraw);
    const int lane = threadIdx.x & 31, wid = threadIdx.x >> 5;
    const int warp_m = (wid >> 2) * 64, warp_n = (wid & 3) * 32;
    const int row0 = blockIdx.y * 128, col0 = blockIdx.x * 128;

    float acc[4][4][4] = {};
    gemm128_f16<false, 3>(g_pxh, nullptr, g_wvoh, row0, col0, DIM, 0, DIM, sm, acc);

    #pragma unroll
    for (int mt = 0; mt < 4; mt++) {
        int r0 = row0 + warp_m + mt*16 + (lane >> 2);
        #pragma unroll
        for (int nt = 0; nt < 4; nt++) {
            int col = col0 + warp_n + nt*8 + (lane & 3) * 2;
            float2 bb = *(const float2*)(bo + col);
            #pragma unroll
            for (int half = 0; half < 2; half++) {
                int r = r0 + half*8;
                float2 f2 = {bb.x - NEGC * acc[mt][nt][2*half],
                             bb.y - NEGC * acc[mt][nt][2*half+1]};
                *(float2*)(out + (size_t)r * DIM + col) = f2;
            }
        }
    }
}

// ---------------------------------------------------------------------------
extern "C" void kernel_launch(void* const* d_in, const int* in_sizes, int n_in,
                              void* d_out, int out_size)
{
    const float* x  = (const float*)d_in[0];
    const float* wv = (const float*)d_in[3];
    const float* wo = (const float*)d_in[4];
    const float* bo = (const float*)d_in[5];
    float* out = (float*)d_out;

    cudaFuncSetAttribute(wvo_kernel,
                         cudaFuncAttributeMaxDynamicSharedMemorySize, SM_X2);
    cudaFuncSetAttribute(cum_out_kernel,
                         cudaFuncAttributeMaxDynamicSharedMemorySize, SM_X1);

    split_wo_kernel<<<DIM*DIM/(256*4), 256>>>(wo);
    transpose_wv_kernel<<<dim3(32, 32), 256>>>(wv);
    prefix_x_a_kernel<<<dim3(NB, NCH), 256>>>(x);
    prefix_x_b_kernel<<<dim3(NB, NCH), 256>>>(x);
    wvo_kernel<<<dim3(DIM/128, DIM/128, WVO_SPLIT), 256, SM_X2>>>();
    wvo_reduce_kernel<<<DIM*DIM/(256*4), 256>>>();
    cum_out_kernel<<<dim3(DIM/128, NS/128), 256, SM_X1>>>(bo, out);
}